// round 5
// baseline (speedup 1.0000x reference)
#include <cuda_runtime.h>
#include <cuda_bf16.h>
#include <cstdint>

#define NN 10000
#define EE 320000
#define DD 256

// ---------------- scratch (static device globals; no allocation) ----------------
__device__ float g_esrc[NN * DD];
__device__ float g_edst[NN * DD];
__device__ float g_fsrc[NN * DD];
__device__ float g_agg[NN * DD];
__device__ float g_outdeg[NN];
__device__ float g_indeg[NN];
// edge features pre-split to bf16 hi/lo, pre-swizzled per (tile,kc) in SMEM layout:
// index = (((tile*4 + kc)*128 + row)*8 + (koct ^ (row&7))) * 8 elems
__device__ unsigned short g_Ehi[EE * DD];
__device__ unsigned short g_Elo[EE * DD];
// w_edge^T split to bf16 hi/lo, pre-swizzled per (half,kc):
// index = (((half*4 + kc)*128 + nrow)*8 + (koct ^ (nrow&7))) * 8 elems
__device__ unsigned short g_Bswhi[2 * 4 * 128 * 64];
__device__ unsigned short g_Bswlo[2 * 4 * 128 * 64];

// ---------------- helpers ----------------
__device__ __forceinline__ uint32_t smem_to_u32(const void* p) {
    uint32_t a;
    asm("{ .reg .u64 t; cvta.to.shared.u64 t, %1; cvt.u32.u64 %0, t; }" : "=r"(a) : "l"(p));
    return a;
}
__device__ __forceinline__ void ldm_x4(uint32_t& r0, uint32_t& r1, uint32_t& r2, uint32_t& r3,
                                       uint32_t addr) {
    asm volatile("ldmatrix.sync.aligned.m8n8.x4.shared.b16 {%0,%1,%2,%3}, [%4];"
                 : "=r"(r0), "=r"(r1), "=r"(r2), "=r"(r3) : "r"(addr));
}
__device__ __forceinline__ void mma16816(float* c, const uint32_t* a, const uint32_t* b) {
    asm volatile(
        "mma.sync.aligned.m16n8k16.row.col.f32.bf16.bf16.f32 "
        "{%0,%1,%2,%3}, {%4,%5,%6,%7}, {%8,%9}, {%0,%1,%2,%3};"
        : "+f"(c[0]), "+f"(c[1]), "+f"(c[2]), "+f"(c[3])
        : "r"(a[0]), "r"(a[1]), "r"(a[2]), "r"(a[3]), "r"(b[0]), "r"(b[1]));
}
#define CP_ASYNC16(saddr, gptr) \
    asm volatile("cp.async.cg.shared.global [%0], [%1], 16;" :: "r"(saddr), "l"(gptr) : "memory")
#define CP_COMMIT() asm volatile("cp.async.commit_group;" ::: "memory")
#define CP_WAIT0()  asm volatile("cp.async.wait_group 0;" ::: "memory")

__device__ __forceinline__ uint32_t split_pair(float a, float b, uint32_t& lo) {
    __nv_bfloat16 ha = __float2bfloat16(a), hb = __float2bfloat16(b);
    __nv_bfloat16 la = __float2bfloat16(a - __bfloat162float(ha));
    __nv_bfloat16 lb = __float2bfloat16(b - __bfloat162float(hb));
    lo = ((uint32_t)__bfloat16_as_ushort(lb) << 16) | (uint32_t)__bfloat16_as_ushort(la);
    return ((uint32_t)__bfloat16_as_ushort(hb) << 16) | (uint32_t)__bfloat16_as_ushort(ha);
}

// ---------------- prep: edge feats -> bf16 hi/lo, swizzled ----------------
__global__ void prep_e_kernel(const float* __restrict__ edgef) {
    int t = blockIdx.x * blockDim.x + threadIdx.x;   // 10.24M threads, 8 elems each
    if (t >= EE * 32) return;
    int row_g = t >> 5;          // edge id
    int koct_g = t & 31;         // 8-elem group in K=256
    int tile = row_g >> 7, row = row_g & 127;
    int kc = koct_g >> 3, koct = koct_g & 7;
    const float* p = edgef + (size_t)row_g * DD + koct_g * 8;
    float4 x0 = *(const float4*)p;
    float4 x1 = *(const float4*)(p + 4);
    uint32_t l0, l1, l2, l3;
    uint32_t h0 = split_pair(x0.x, x0.y, l0);
    uint32_t h1 = split_pair(x0.z, x0.w, l1);
    uint32_t h2 = split_pair(x1.x, x1.y, l2);
    uint32_t h3 = split_pair(x1.z, x1.w, l3);
    int di = (((tile * 4 + kc) * 128 + row) * 8 + (koct ^ (row & 7)));
    ((uint4*)g_Ehi)[di] = make_uint4(h0, h1, h2, h3);
    ((uint4*)g_Elo)[di] = make_uint4(l0, l1, l2, l3);
}

// ---------------- prep: weights -> transposed bf16 hi/lo, swizzled ----------------
__global__ void prep_w_kernel(const float* __restrict__ w_edge) {
    int t = blockIdx.x * blockDim.x + threadIdx.x;   // 8192 threads
    if (t >= 8192) return;
    int n = t & 255;            // output column
    int koct_g = t >> 8;        // 0..31
    int kc = koct_g >> 3, koct = koct_g & 7;
    int half = n >> 7, nrow = n & 127;
    uint32_t h[4], l[4];
    #pragma unroll
    for (int j = 0; j < 4; j++) {
        int k = koct_g * 8 + 2 * j;
        float a = w_edge[(size_t)k * DD + n];
        float b = w_edge[(size_t)(k + 1) * DD + n];
        h[j] = split_pair(a, b, l[j]);
    }
    int di = (((half * 4 + kc) * 128 + nrow) * 8 + (koct ^ (nrow & 7)));
    ((uint4*)g_Bswhi)[di] = make_uint4(h[0], h[1], h[2], h[3]);
    ((uint4*)g_Bswlo)[di] = make_uint4(l[0], l[1], l[2], l[3]);
}

// ---------------- SMEM layout (XOR swizzle, no padding) ----------------
// B: hi 16KB @0, lo 16KB @16384. A stages: stage s @ 32768 + s*32768 (hi 16KB, lo 16KB)
static constexpr int S_BHI = 0;
static constexpr int S_BLO = 16384;
static constexpr int S_A0  = 32768;
static constexpr int S_TOTAL = 98304;       // 96KB -> 2 CTAs/SM
static constexpr int DS_STRIDE = 136;       // floats; D stage 128*136*4 = 69632 (reuses smem)

// ---------------- edge GEMM (pipelined mma.sync bf16x3) + fused epilogue ----------------
__global__ void __launch_bounds__(256, 2)
edge_mma_kernel(const int* __restrict__ src, const int* __restrict__ dst,
                const float* __restrict__ b_edge, float* __restrict__ m_out)
{
    extern __shared__ char smem[];
    const uint32_t sb = smem_to_u32(smem);
    const int tid = threadIdx.x;
    const int lane = tid & 31;
    const int wid = tid >> 5;
    const int warp_m = wid & 3;
    const int warp_n = wid >> 2;
    const int tile = blockIdx.x;
    const int half = blockIdx.y;

    const uint4* gAhi = (const uint4*)g_Ehi + (size_t)tile * 4 * 1024;
    const uint4* gAlo = (const uint4*)g_Elo + (size_t)tile * 4 * 1024;
    const uint4* gBhi = (const uint4*)g_Bswhi + (size_t)half * 4 * 1024;
    const uint4* gBlo = (const uint4*)g_Bswlo + (size_t)half * 4 * 1024;

    float acc[2][8][4];
    #pragma unroll
    for (int mt = 0; mt < 2; mt++)
        #pragma unroll
        for (int nt = 0; nt < 8; nt++)
            #pragma unroll
            for (int i = 0; i < 4; i++) acc[mt][nt][i] = 0.f;

    // issue A(0) + B(0)
    #pragma unroll
    for (int i = 0; i < 4; i++) {
        int idx = tid + i * 256;                      // 0..1023 (16B units)
        CP_ASYNC16(sb + S_A0 + idx * 16,         gAhi + idx);
        CP_ASYNC16(sb + S_A0 + 16384 + idx * 16, gAlo + idx);
        CP_ASYNC16(sb + S_BHI + idx * 16,        gBhi + idx);
        CP_ASYNC16(sb + S_BLO + idx * 16,        gBlo + idx);
    }
    CP_COMMIT();

    // ldmatrix lane address components
    const uint32_t a_row = (uint32_t)(lane & 15);        // + warp_m*32 + mt*16
    const uint32_t a_kh  = (uint32_t)(lane >> 4);        // 0/1
    const uint32_t b_nl  = (uint32_t)((lane & 7) + ((lane >> 4) << 3));
    const uint32_t b_kh  = (uint32_t)((lane >> 3) & 1);

    for (int kc = 0; kc < 4; kc++) {
        CP_WAIT0();
        __syncthreads();
        const uint32_t stA = sb + S_A0 + (uint32_t)(kc & 1) * 32768;

        // prefetch A(kc+1) into other stage (hidden under MMA phase)
        if (kc < 3) {
            const uint32_t stN = sb + S_A0 + (uint32_t)((kc + 1) & 1) * 32768;
            #pragma unroll
            for (int i = 0; i < 4; i++) {
                int idx = tid + i * 256;
                CP_ASYNC16(stN + idx * 16,         gAhi + (kc + 1) * 1024 + idx);
                CP_ASYNC16(stN + 16384 + idx * 16, gAlo + (kc + 1) * 1024 + idx);
            }
            CP_COMMIT();
        }

        // ---- MMA over 4 k16 steps of this chunk ----
        #pragma unroll
        for (int ks = 0; ks < 4; ks++) {
            uint32_t ah[2][4], al[2][4];
            #pragma unroll
            for (int mt = 0; mt < 2; mt++) {
                uint32_t row = (uint32_t)(warp_m * 32 + mt * 16) + a_row;
                uint32_t koct = (uint32_t)ks * 2 + a_kh;
                uint32_t off = row * 128 + ((koct ^ (row & 7)) << 4);
                ldm_x4(ah[mt][0], ah[mt][1], ah[mt][2], ah[mt][3], stA + off);
                ldm_x4(al[mt][0], al[mt][1], al[mt][2], al[mt][3], stA + 16384 + off);
            }
            #pragma unroll
            for (int j = 0; j < 4; j++) {
                uint32_t nrow = (uint32_t)(warp_n * 64 + j * 16) + b_nl;
                uint32_t koct = (uint32_t)ks * 2 + b_kh;
                uint32_t off = nrow * 128 + ((koct ^ (nrow & 7)) << 4);
                uint32_t bh[4], bl[4];
                ldm_x4(bh[0], bh[1], bh[2], bh[3], sb + S_BHI + off);
                ldm_x4(bl[0], bl[1], bl[2], bl[3], sb + S_BLO + off);
                #pragma unroll
                for (int mt = 0; mt < 2; mt++) {
                    mma16816(acc[mt][2 * j + 0], ah[mt], bh + 0);
                    mma16816(acc[mt][2 * j + 1], ah[mt], bh + 2);
                    mma16816(acc[mt][2 * j + 0], ah[mt], bl + 0);
                    mma16816(acc[mt][2 * j + 1], ah[mt], bl + 2);
                    mma16816(acc[mt][2 * j + 0], al[mt], bh + 0);
                    mma16816(acc[mt][2 * j + 1], al[mt], bh + 2);
                }
            }
        }
        __syncthreads();   // all warps done reading B before overwrite

        // issue B(kc+1) (short L2-hot exposure at next wait)
        if (kc < 3) {
            #pragma unroll
            for (int i = 0; i < 4; i++) {
                int idx = tid + i * 256;
                CP_ASYNC16(sb + S_BHI + idx * 16, gBhi + (kc + 1) * 1024 + idx);
                CP_ASYNC16(sb + S_BLO + idx * 16, gBlo + (kc + 1) * 1024 + idx);
            }
            CP_COMMIT();
        }
    }

    // ---- stage D to smem (reuses tile buffers) ----
    {
        float* Ds = (float*)smem;
        const int g = lane >> 2, tg = lane & 3;
        #pragma unroll
        for (int mt = 0; mt < 2; mt++) {
            int r0 = warp_m * 32 + mt * 16 + g;
            #pragma unroll
            for (int nt = 0; nt < 8; nt++) {
                int c = warp_n * 64 + nt * 8 + tg * 2;
                *(float2*)(Ds + r0 * DS_STRIDE + c) = make_float2(acc[mt][nt][0], acc[mt][nt][1]);
                *(float2*)(Ds + (r0 + 8) * DS_STRIDE + c) = make_float2(acc[mt][nt][2], acc[mt][nt][3]);
            }
        }
    }
    __syncthreads();

    // ---- fused epilogue ----
    {
        const float* Ds = (const float*)smem;
        const int row = tid >> 1;
        const int chalf = (tid & 1) * 64;
        const int e = tile * 128 + row;
        const int nBase = half * 128;
        const int s = src[e], d = dst[e];
        const float* pe1 = g_esrc + (size_t)s * DD + nBase;
        const float* pe2 = g_edst + (size_t)d * DD + nBase;
        const float* pf  = g_fsrc + (size_t)s * DD + nBase;
        float* pm = m_out + (size_t)e * DD + nBase;
        float* pa = g_agg + (size_t)d * DD + nBase;
        const float* pb = b_edge + nBase;
        const float* dr = Ds + row * DS_STRIDE;

        #pragma unroll
        for (int j = 0; j < 16; j++) {
            int c = chalf + j * 4;
            float4 dv = *(const float4*)(dr + c);
            float4 bb = *(const float4*)(pb + c);
            float4 e1 = *(const float4*)(pe1 + c);
            float4 e2 = *(const float4*)(pe2 + c);
            float4 f  = *(const float4*)(pf + c);
            float4 mv;
            mv.x = dv.x + bb.x + e1.x + e2.x;
            mv.y = dv.y + bb.y + e1.y + e2.y;
            mv.z = dv.z + bb.z + e1.z + e2.z;
            mv.w = dv.w + bb.w + e1.w + e2.w;
            *(float4*)(pm + c) = mv;
            float s0 = f.x / (1.f + __expf(-mv.x));
            float s1 = f.y / (1.f + __expf(-mv.y));
            float s2 = f.z / (1.f + __expf(-mv.z));
            float s3 = f.w / (1.f + __expf(-mv.w));
            asm volatile("red.global.add.v4.f32 [%0], {%1,%2,%3,%4};"
                         :: "l"(pa + c), "f"(s0), "f"(s1), "f"(s2), "f"(s3) : "memory");
        }
    }
}

// ---------------- small kernels ----------------
__global__ void zero_kernel() {
    int i = blockIdx.x * blockDim.x + threadIdx.x;
    if (i < NN * DD) g_agg[i] = 0.f;
    if (i < NN) { g_outdeg[i] = 0.f; g_indeg[i] = 0.f; }
}
__global__ void degree_kernel(const int* __restrict__ src, const int* __restrict__ dst) {
    int e = blockIdx.x * blockDim.x + threadIdx.x;
    if (e < EE) {
        atomicAdd(&g_outdeg[src[e]], 1.f);
        atomicAdd(&g_indeg[dst[e]], 1.f);
    }
}
__global__ void featsrc_kernel(const float* __restrict__ nodef) {
    int i = blockIdx.x * blockDim.x + threadIdx.x;
    if (i < NN * DD) {
        int r = i / DD;
        g_fsrc[i] = nodef[i] * rsqrtf(fmaxf(g_outdeg[r], 1.f));
    }
}

// ---- SIMT GEMM 64x64x16 for node-sized matmuls ----
template <int MODE>
__global__ void __launch_bounds__(256)
gemm_kernel(const float* __restrict__ A_in, const float* __restrict__ B0,
            const float* __restrict__ bias0, const float* __restrict__ B1,
            const float* __restrict__ bias1, float* __restrict__ C, int M,
            const float* __restrict__ nodef)
{
    const float* A = (MODE == 3) ? (const float*)g_agg : A_in;
    const float* B = (MODE == 0 && blockIdx.z) ? B1 : B0;
    const float* bias = (MODE == 0 && blockIdx.z) ? bias1 : bias0;

    constexpr int BM = 64, BN = 64, BK = 16;
    __shared__ float As[BK][BM + 1];
    __shared__ float Bs[BK][BN];

    const int tid = threadIdx.x;
    const int tx = tid & 15, ty = tid >> 4;
    const int bm0 = blockIdx.y * BM, bn0 = blockIdx.x * BN;
    const int lrow = tid >> 2, lk = (tid & 3) * 4;
    const int brow = tid >> 4, bcol = (tid & 15) * 4;

    float acc[4][4];
    #pragma unroll
    for (int i = 0; i < 4; i++)
        #pragma unroll
        for (int j = 0; j < 4; j++) acc[i][j] = 0.f;

    const int ty4 = ty * 4, tx4 = tx * 4;
    for (int k0 = 0; k0 < DD; k0 += BK) {
        float4 av;
        int ar = bm0 + lrow;
        if (ar < M) av = *(const float4*)(A + (size_t)ar * DD + k0 + lk);
        else        av = make_float4(0.f, 0.f, 0.f, 0.f);
        As[lk + 0][lrow] = av.x; As[lk + 1][lrow] = av.y;
        As[lk + 2][lrow] = av.z; As[lk + 3][lrow] = av.w;
        *(float4*)&Bs[brow][bcol] = *(const float4*)(B + (size_t)(k0 + brow) * DD + bn0 + bcol);
        __syncthreads();
        #pragma unroll
        for (int kk = 0; kk < BK; kk++) {
            float a0 = As[kk][ty4 + 0], a1 = As[kk][ty4 + 1];
            float a2 = As[kk][ty4 + 2], a3 = As[kk][ty4 + 3];
            float4 b = *(float4*)&Bs[kk][tx4];
            acc[0][0] += a0 * b.x; acc[0][1] += a0 * b.y; acc[0][2] += a0 * b.z; acc[0][3] += a0 * b.w;
            acc[1][0] += a1 * b.x; acc[1][1] += a1 * b.y; acc[1][2] += a1 * b.z; acc[1][3] += a1 * b.w;
            acc[2][0] += a2 * b.x; acc[2][1] += a2 * b.y; acc[2][2] += a2 * b.z; acc[2][3] += a2 * b.w;
            acc[3][0] += a3 * b.x; acc[3][1] += a3 * b.y; acc[3][2] += a3 * b.z; acc[3][3] += a3 * b.w;
        }
        __syncthreads();
    }

    const float4 bb = *(const float4*)(bias + bn0 + tx4);
    const size_t coloff = (size_t)(bn0 + tx4);
    #pragma unroll
    for (int i = 0; i < 4; i++) {
        int r = bm0 + ty4 + i;
        if (r >= M) continue;
        if (MODE == 0) {
            float4 o;
            o.x = acc[i][0] + bb.x; o.y = acc[i][1] + bb.y;
            o.z = acc[i][2] + bb.z; o.w = acc[i][3] + bb.w;
            float* dstp = blockIdx.z ? g_edst : g_esrc;
            *(float4*)(dstp + (size_t)r * DD + coloff) = o;
        } else {
            float nrm = rsqrtf(fmaxf(g_indeg[r], 1.f));
            const float4 nf = *(const float4*)(nodef + (size_t)r * DD + coloff);
            float4 o;
            o.x = nf.x + acc[i][0] * nrm + bb.x;
            o.y = nf.y + acc[i][1] * nrm + bb.y;
            o.z = nf.z + acc[i][2] * nrm + bb.z;
            o.w = nf.w + acc[i][3] * nrm + bb.w;
            *(float4*)(C + (size_t)r * DD + coloff) = o;
        }
    }
}

extern "C" void kernel_launch(void* const* d_in, const int* in_sizes, int n_in,
                              void* d_out, int out_size) {
    const float* nodef  = (const float*)d_in[0];
    const float* edgef  = (const float*)d_in[1];
    const int*   src    = (const int*)d_in[2];
    const int*   dst    = (const int*)d_in[3];
    const float* weight = (const float*)d_in[4];
    const float* bias   = (const float*)d_in[5];
    const float* w_src  = (const float*)d_in[6];
    const float* b_src  = (const float*)d_in[7];
    const float* w_dst  = (const float*)d_in[8];
    const float* b_dst  = (const float*)d_in[9];
    const float* w_edge = (const float*)d_in[10];
    const float* b_edge = (const float*)d_in[11];

    float* rst   = (float*)d_out;             // [N, D]
    float* m_out = rst + (size_t)NN * DD;     // [E, D]

    static bool attr_set = false;
    if (!attr_set) {
        cudaFuncSetAttribute(edge_mma_kernel, cudaFuncAttributeMaxDynamicSharedMemorySize, S_TOTAL);
        attr_set = true;
    }

    prep_w_kernel<<<32, 256>>>(w_edge);
    prep_e_kernel<<<(EE * 32 + 255) / 256, 256>>>(edgef);
    zero_kernel<<<(NN * DD + 255) / 256, 256>>>();
    degree_kernel<<<(EE + 255) / 256, 256>>>(src, dst);
    {
        dim3 g(DD / 64, (NN + 63) / 64, 2);
        gemm_kernel<0><<<g, 256>>>(nodef, w_src, b_src, w_dst, b_dst, nullptr, NN, nullptr);
    }
    featsrc_kernel<<<(NN * DD + 255) / 256, 256>>>(nodef);
    {
        dim3 g(EE / 128, 2);
        edge_mma_kernel<<<g, 256, S_TOTAL>>>(src, dst, b_edge, m_out);
    }
    {
        dim3 g(DD / 64, (NN + 63) / 64, 1);
        gemm_kernel<3><<<g, 256>>>(nullptr, weight, bias, nullptr, nullptr, rst, NN, nodef);
    }
}

// round 6
// speedup vs baseline: 1.0876x; 1.0876x over previous
#include <cuda_runtime.h>
#include <cuda_bf16.h>
#include <cstdint>

#define NN 10000
#define EE 320000
#define DD 256

// ---------------- scratch (static device globals; no allocation) ----------------
__device__ float g_esrc[NN * DD];
__device__ float g_edst[NN * DD];
__device__ float g_fsrc[NN * DD];
__device__ float g_agg[NN * DD];
__device__ float g_outdeg[NN];
__device__ float g_indeg[NN];
// w_edge^T split to bf16 hi/lo, pre-swizzled per kc:
// 16B-unit index = (kc*256 + nrow)*8 + (koct ^ (nrow&7))
__device__ unsigned short g_Bswhi[4 * 256 * 64];
__device__ unsigned short g_Bswlo[4 * 256 * 64];

// ---------------- helpers ----------------
__device__ __forceinline__ uint32_t smem_to_u32(const void* p) {
    uint32_t a;
    asm("{ .reg .u64 t; cvta.to.shared.u64 t, %1; cvt.u32.u64 %0, t; }" : "=r"(a) : "l"(p));
    return a;
}
__device__ __forceinline__ void ldm_x4(uint32_t& r0, uint32_t& r1, uint32_t& r2, uint32_t& r3,
                                       uint32_t addr) {
    asm volatile("ldmatrix.sync.aligned.m8n8.x4.shared.b16 {%0,%1,%2,%3}, [%4];"
                 : "=r"(r0), "=r"(r1), "=r"(r2), "=r"(r3) : "r"(addr));
}
__device__ __forceinline__ void mma16816(float* c, const uint32_t* a, const uint32_t* b) {
    asm volatile(
        "mma.sync.aligned.m16n8k16.row.col.f32.bf16.bf16.f32 "
        "{%0,%1,%2,%3}, {%4,%5,%6,%7}, {%8,%9}, {%0,%1,%2,%3};"
        : "+f"(c[0]), "+f"(c[1]), "+f"(c[2]), "+f"(c[3])
        : "r"(a[0]), "r"(a[1]), "r"(a[2]), "r"(a[3]), "r"(b[0]), "r"(b[1]));
}
#define CP_ASYNC16(saddr, gptr) \
    asm volatile("cp.async.cg.shared.global [%0], [%1], 16;" :: "r"(saddr), "l"(gptr) : "memory")
#define CP_COMMIT() asm volatile("cp.async.commit_group;" ::: "memory")
#define CP_WAIT0()  asm volatile("cp.async.wait_group 0;" ::: "memory")

__device__ __forceinline__ uint32_t split_pair(float a, float b, uint32_t& lo) {
    __nv_bfloat16 ha = __float2bfloat16(a), hb = __float2bfloat16(b);
    __nv_bfloat16 la = __float2bfloat16(a - __bfloat162float(ha));
    __nv_bfloat16 lb = __float2bfloat16(b - __bfloat162float(hb));
    lo = ((uint32_t)__bfloat16_as_ushort(lb) << 16) | (uint32_t)__bfloat16_as_ushort(la);
    return ((uint32_t)__bfloat16_as_ushort(hb) << 16) | (uint32_t)__bfloat16_as_ushort(ha);
}

// ---------------- launch 0: weight prep + zero (fused) ----------------
__global__ void fuse0_kernel(const float* __restrict__ w_edge) {
    int t = blockIdx.x * blockDim.x + threadIdx.x;
    if (t < NN * DD) g_agg[t] = 0.f;
    if (t < NN) { g_outdeg[t] = 0.f; g_indeg[t] = 0.f; }
    if (t < 8192) {
        int n = t & 255;
        int koct_g = t >> 8;          // 0..31
        int kc = koct_g >> 3, koct = koct_g & 7;
        uint32_t h[4], l[4];
        #pragma unroll
        for (int j = 0; j < 4; j++) {
            int k = koct_g * 8 + 2 * j;
            float a = w_edge[(size_t)k * DD + n];
            float b = w_edge[(size_t)(k + 1) * DD + n];
            h[j] = split_pair(a, b, l[j]);
        }
        int di = (kc * 256 + n) * 8 + (koct ^ (n & 7));
        ((uint4*)g_Bswhi)[di] = make_uint4(h[0], h[1], h[2], h[3]);
        ((uint4*)g_Bswlo)[di] = make_uint4(l[0], l[1], l[2], l[3]);
    }
}

// ---------------- launch 1: degrees ----------------
__global__ void degree_kernel(const int* __restrict__ src, const int* __restrict__ dst) {
    int e = blockIdx.x * blockDim.x + threadIdx.x;
    if (e < EE) {
        atomicAdd(&g_outdeg[src[e]], 1.f);
        atomicAdd(&g_indeg[dst[e]], 1.f);
    }
}

// ---------------- SMEM layout for edge kernel ----------------
static constexpr int S_BHI  = 0;        // 32KB: B chunk hi, 256 rows x 128B swizzled
static constexpr int S_BLO  = 32768;    // 32KB: B chunk lo
static constexpr int S_AHI  = 65536;    // 8KB:  A chunk hi, 64 rows x 128B swizzled
static constexpr int S_ALO  = 73728;    // 8KB:  A chunk lo
static constexpr int S_AF32 = 81920;    // 16KB: A chunk fp32 staging, 64 rows x 256B
static constexpr int S_TOTAL = 98304;   // 96KB -> 2 CTAs/SM
static constexpr int DS_STRIDE = 260;   // floats; D stage 64 x 260 x 4B = 66560 (reuse)

// ---------------- launch 3: edge GEMM (mma.sync bf16x3) + fused epilogue ----------------
__global__ void __launch_bounds__(256, 2)
edge_mma_kernel(const float* __restrict__ edgef, const int* __restrict__ src,
                const int* __restrict__ dst, const float* __restrict__ b_edge,
                float* __restrict__ m_out)
{
    extern __shared__ char smem[];
    const uint32_t sb = smem_to_u32(smem);
    const int tid = threadIdx.x;
    const int lane = tid & 31;
    const int wid = tid >> 5;
    const int warp_m = wid & 1;       // 0/1 -> rows 0-31 / 32-63
    const int warp_n = wid >> 1;      // 0..3 -> 64-col group
    const int tile = blockIdx.x;      // 64 edges per tile

    float acc[2][8][4];
    #pragma unroll
    for (int mt = 0; mt < 2; mt++)
        #pragma unroll
        for (int nt = 0; nt < 8; nt++)
            #pragma unroll
            for (int i = 0; i < 4; i++) acc[mt][nt][i] = 0.f;

    const uint4* gBhi = (const uint4*)g_Bswhi;
    const uint4* gBlo = (const uint4*)g_Bswlo;
    const float* gA = edgef + (size_t)tile * 64 * DD;

    // issue A_f32(0) + B(0)
    #pragma unroll
    for (int i = 0; i < 4; i++) {      // A: 1024 16B units
        int idx = tid + i * 256;
        CP_ASYNC16(sb + S_AF32 + idx * 16, gA + (idx >> 4) * 256 + (idx & 15) * 4);
    }
    #pragma unroll
    for (int i = 0; i < 8; i++) {      // B: 2048 units each
        int idx = tid + i * 256;
        CP_ASYNC16(sb + S_BHI + idx * 16, gBhi + idx);
        CP_ASYNC16(sb + S_BLO + idx * 16, gBlo + idx);
    }
    CP_COMMIT();

    const uint32_t a_row = (uint32_t)(lane & 15);
    const uint32_t a_kh  = (uint32_t)(lane >> 4);
    const uint32_t b_nl  = (uint32_t)((lane & 7) + ((lane >> 4) << 3));
    const uint32_t b_kh  = (uint32_t)((lane >> 3) & 1);

    for (int kc = 0; kc < 4; kc++) {
        CP_WAIT0();
        __syncthreads();

        // ---- convert A chunk: SMEM fp32 -> bf16 hi/lo swizzled ----
        const float* Af = (const float*)(smem + S_AF32);
        #pragma unroll
        for (int i = 0; i < 2; i++) {
            int g = tid + i * 256;            // 0..511 groups of 8 elems
            int row = g >> 3, koct = g & 7;
            const float* p = Af + row * 64 + koct * 8;
            float4 x0 = *(const float4*)p;
            float4 x1 = *(const float4*)(p + 4);
            uint32_t l0, l1, l2, l3;
            uint32_t h0 = split_pair(x0.x, x0.y, l0);
            uint32_t h1 = split_pair(x0.z, x0.w, l1);
            uint32_t h2 = split_pair(x1.x, x1.y, l2);
            uint32_t h3 = split_pair(x1.z, x1.w, l3);
            uint32_t off = (uint32_t)row * 128u + (uint32_t)((koct ^ (row & 7)) << 4);
            *(uint4*)(smem + S_AHI + off) = make_uint4(h0, h1, h2, h3);
            *(uint4*)(smem + S_ALO + off) = make_uint4(l0, l1, l2, l3);
        }
        __syncthreads();    // A bf16 ready; A_f32 stage free

        // prefetch A_f32(kc+1) — lands during MMA phase
        if (kc < 3) {
            const float* gAn = gA + (kc + 1) * 64;
            #pragma unroll
            for (int i = 0; i < 4; i++) {
                int idx = tid + i * 256;
                CP_ASYNC16(sb + S_AF32 + idx * 16, gAn + (idx >> 4) * 256 + (idx & 15) * 4);
            }
            CP_COMMIT();
        }

        // ---- MMA: 4 k16 steps ----
        #pragma unroll
        for (int ks = 0; ks < 4; ks++) {
            uint32_t ah[2][4], al[2][4];
            #pragma unroll
            for (int mt = 0; mt < 2; mt++) {
                uint32_t row = (uint32_t)(warp_m * 32 + mt * 16) + a_row;
                uint32_t koct = (uint32_t)ks * 2 + a_kh;
                uint32_t off = row * 128 + ((koct ^ (row & 7)) << 4);
                ldm_x4(ah[mt][0], ah[mt][1], ah[mt][2], ah[mt][3], sb + S_AHI + off);
                ldm_x4(al[mt][0], al[mt][1], al[mt][2], al[mt][3], sb + S_ALO + off);
            }
            #pragma unroll
            for (int j = 0; j < 4; j++) {
                uint32_t nrow = (uint32_t)(warp_n * 64 + j * 16) + b_nl;
                uint32_t koct = (uint32_t)ks * 2 + b_kh;
                uint32_t off = nrow * 128 + ((koct ^ (nrow & 7)) << 4);
                uint32_t bh[4], bl[4];
                ldm_x4(bh[0], bh[1], bh[2], bh[3], sb + S_BHI + off);
                ldm_x4(bl[0], bl[1], bl[2], bl[3], sb + S_BLO + off);
                #pragma unroll
                for (int mt = 0; mt < 2; mt++) {
                    mma16816(acc[mt][2 * j + 0], ah[mt], bh + 0);
                    mma16816(acc[mt][2 * j + 1], ah[mt], bh + 2);
                    mma16816(acc[mt][2 * j + 0], ah[mt], bl + 0);
                    mma16816(acc[mt][2 * j + 1], ah[mt], bl + 2);
                    mma16816(acc[mt][2 * j + 0], al[mt], bh + 0);
                    mma16816(acc[mt][2 * j + 1], al[mt], bh + 2);
                }
            }
        }
        __syncthreads();    // B smem free

        if (kc < 3) {
            #pragma unroll
            for (int i = 0; i < 8; i++) {
                int idx = tid + i * 256;
                CP_ASYNC16(sb + S_BHI + idx * 16, gBhi + (kc + 1) * 2048 + idx);
                CP_ASYNC16(sb + S_BLO + idx * 16, gBlo + (kc + 1) * 2048 + idx);
            }
            CP_COMMIT();
        }
    }

    // ---- stage D (64 x 256 fp32, stride 260) ----
    {
        float* Ds = (float*)smem;
        const int g = lane >> 2, tg = lane & 3;
        #pragma unroll
        for (int mt = 0; mt < 2; mt++) {
            int r0 = warp_m * 32 + mt * 16 + g;
            #pragma unroll
            for (int nt = 0; nt < 8; nt++) {
                int c = warp_n * 64 + nt * 8 + tg * 2;
                *(float2*)(Ds + r0 * DS_STRIDE + c) = make_float2(acc[mt][nt][0], acc[mt][nt][1]);
                *(float2*)(Ds + (r0 + 8) * DS_STRIDE + c) = make_float2(acc[mt][nt][2], acc[mt][nt][3]);
            }
        }
    }
    __syncthreads();

    // ---- fused epilogue: 4 threads per edge row, 64-col quarters ----
    {
        const float* Ds = (const float*)smem;
        const int row = tid >> 2;
        const int q = (tid & 3) * 64;
        const int e = tile * 64 + row;
        const int s = src[e], d = dst[e];
        const float* pe1 = g_esrc + (size_t)s * DD;
        const float* pe2 = g_edst + (size_t)d * DD;
        const float* pf  = g_fsrc + (size_t)s * DD;
        float* pm = m_out + (size_t)e * DD;
        float* pa = g_agg + (size_t)d * DD;
        const float* dr = Ds + row * DS_STRIDE;

        #pragma unroll
        for (int j = 0; j < 16; j++) {
            int c = q + j * 4;
            float4 dv = *(const float4*)(dr + c);
            float4 bb = *(const float4*)(b_edge + c);
            float4 e1 = *(const float4*)(pe1 + c);
            float4 e2 = *(const float4*)(pe2 + c);
            float4 f  = *(const float4*)(pf + c);
            float4 mv;
            mv.x = dv.x + bb.x + e1.x + e2.x;
            mv.y = dv.y + bb.y + e1.y + e2.y;
            mv.z = dv.z + bb.z + e1.z + e2.z;
            mv.w = dv.w + bb.w + e1.w + e2.w;
            *(float4*)(pm + c) = mv;
            float s0 = f.x / (1.f + __expf(-mv.x));
            float s1 = f.y / (1.f + __expf(-mv.y));
            float s2 = f.z / (1.f + __expf(-mv.z));
            float s3 = f.w / (1.f + __expf(-mv.w));
            asm volatile("red.global.add.v4.f32 [%0], {%1,%2,%3,%4};"
                         :: "l"(pa + c), "f"(s0), "f"(s1), "f"(s2), "f"(s3) : "memory");
        }
    }
}

// ---- SIMT GEMM 64x64x16 for node-sized matmuls ----
// MODE 0: z=0 -> esrc (+ fsrc rows), z=1 -> edst
// MODE 3: rst = nodef + (g_agg@weight)*indeg^-1/2 + bias
template <int MODE>
__global__ void __launch_bounds__(256)
gemm_kernel(const float* __restrict__ A_in, const float* __restrict__ B0,
            const float* __restrict__ bias0, const float* __restrict__ B1,
            const float* __restrict__ bias1, float* __restrict__ C, int M,
            const float* __restrict__ nodef)
{
    const float* A = (MODE == 3) ? (const float*)g_agg : A_in;
    const float* B = (MODE == 0 && blockIdx.z) ? B1 : B0;
    const float* bias = (MODE == 0 && blockIdx.z) ? bias1 : bias0;

    constexpr int BM = 64, BN = 64, BK = 16;
    __shared__ float As[BK][BM + 1];
    __shared__ float Bs[BK][BN];

    const int tid = threadIdx.x;
    const int tx = tid & 15, ty = tid >> 4;
    const int bm0 = blockIdx.y * BM, bn0 = blockIdx.x * BN;
    const int lrow = tid >> 2, lk = (tid & 3) * 4;
    const int brow = tid >> 4, bcol = (tid & 15) * 4;

    float acc[4][4];
    #pragma unroll
    for (int i = 0; i < 4; i++)
        #pragma unroll
        for (int j = 0; j < 4; j++) acc[i][j] = 0.f;

    const int ty4 = ty * 4, tx4 = tx * 4;
    for (int k0 = 0; k0 < DD; k0 += BK) {
        float4 av;
        int ar = bm0 + lrow;
        if (ar < M) av = *(const float4*)(A + (size_t)ar * DD + k0 + lk);
        else        av = make_float4(0.f, 0.f, 0.f, 0.f);
        As[lk + 0][lrow] = av.x; As[lk + 1][lrow] = av.y;
        As[lk + 2][lrow] = av.z; As[lk + 3][lrow] = av.w;
        *(float4*)&Bs[brow][bcol] = *(const float4*)(B + (size_t)(k0 + brow) * DD + bn0 + bcol);
        __syncthreads();
        #pragma unroll
        for (int kk = 0; kk < BK; kk++) {
            float a0 = As[kk][ty4 + 0], a1 = As[kk][ty4 + 1];
            float a2 = As[kk][ty4 + 2], a3 = As[kk][ty4 + 3];
            float4 b = *(float4*)&Bs[kk][tx4];
            acc[0][0] += a0 * b.x; acc[0][1] += a0 * b.y; acc[0][2] += a0 * b.z; acc[0][3] += a0 * b.w;
            acc[1][0] += a1 * b.x; acc[1][1] += a1 * b.y; acc[1][2] += a1 * b.z; acc[1][3] += a1 * b.w;
            acc[2][0] += a2 * b.x; acc[2][1] += a2 * b.y; acc[2][2] += a2 * b.z; acc[2][3] += a2 * b.w;
            acc[3][0] += a3 * b.x; acc[3][1] += a3 * b.y; acc[3][2] += a3 * b.z; acc[3][3] += a3 * b.w;
        }
        __syncthreads();
    }

    const float4 bb = *(const float4*)(bias + bn0 + tx4);
    const size_t coloff = (size_t)(bn0 + tx4);
    #pragma unroll
    for (int i = 0; i < 4; i++) {
        int r = bm0 + ty4 + i;
        if (r >= M) continue;
        if (MODE == 0) {
            float4 o;
            o.x = acc[i][0] + bb.x; o.y = acc[i][1] + bb.y;
            o.z = acc[i][2] + bb.z; o.w = acc[i][3] + bb.w;
            float* dstp = blockIdx.z ? g_edst : g_esrc;
            *(float4*)(dstp + (size_t)r * DD + coloff) = o;
            if (blockIdx.z == 0) {   // fused feat_src for this (row, col) range
                float nrm = rsqrtf(fmaxf(g_outdeg[r], 1.f));
                const float4 nf = *(const float4*)(nodef + (size_t)r * DD + coloff);
                float4 fo;
                fo.x = nf.x * nrm; fo.y = nf.y * nrm;
                fo.z = nf.z * nrm; fo.w = nf.w * nrm;
                *(float4*)(g_fsrc + (size_t)r * DD + coloff) = fo;
            }
        } else {
            float nrm = rsqrtf(fmaxf(g_indeg[r], 1.f));
            const float4 nf = *(const float4*)(nodef + (size_t)r * DD + coloff);
            float4 o;
            o.x = nf.x + acc[i][0] * nrm + bb.x;
            o.y = nf.y + acc[i][1] * nrm + bb.y;
            o.z = nf.z + acc[i][2] * nrm + bb.z;
            o.w = nf.w + acc[i][3] * nrm + bb.w;
            *(float4*)(C + (size_t)r * DD + coloff) = o;
        }
    }
}

extern "C" void kernel_launch(void* const* d_in, const int* in_sizes, int n_in,
                              void* d_out, int out_size) {
    const float* nodef  = (const float*)d_in[0];
    const float* edgef  = (const float*)d_in[1];
    const int*   src    = (const int*)d_in[2];
    const int*   dst    = (const int*)d_in[3];
    const float* weight = (const float*)d_in[4];
    const float* bias   = (const float*)d_in[5];
    const float* w_src  = (const float*)d_in[6];
    const float* b_src  = (const float*)d_in[7];
    const float* w_dst  = (const float*)d_in[8];
    const float* b_dst  = (const float*)d_in[9];
    const float* w_edge = (const float*)d_in[10];
    const float* b_edge = (const float*)d_in[11];

    float* rst   = (float*)d_out;             // [N, D]
    float* m_out = rst + (size_t)NN * DD;     // [E, D]

    static bool attr_set = false;
    if (!attr_set) {
        cudaFuncSetAttribute(edge_mma_kernel, cudaFuncAttributeMaxDynamicSharedMemorySize, S_TOTAL);
        attr_set = true;
    }

    // launch 0: weight prep + zero
    fuse0_kernel<<<(NN * DD + 255) / 256, 256>>>(w_edge);
    // launch 1: degrees
    degree_kernel<<<(EE + 255) / 256, 256>>>(src, dst);
    // launch 2: e_src (+fsrc) / e_dst
    {
        dim3 g(DD / 64, (NN + 63) / 64, 2);
        gemm_kernel<0><<<g, 256>>>(nodef, w_src, b_src, w_dst, b_dst, nullptr, NN, nodef);
    }
    // launch 3 (profiled): edge GEMM + fused epilogue
    edge_mma_kernel<<<EE / 64, 256, S_TOTAL>>>(edgef, src, dst, b_edge, m_out);
    // launch 4: final projection + norm + bias + residual
    {
        dim3 g(DD / 64, (NN + 63) / 64, 1);
        gemm_kernel<3><<<g, 256>>>(nullptr, weight, bias, nullptr, nullptr, rst, NN, nodef);
    }
}

// round 7
// speedup vs baseline: 1.2651x; 1.1632x over previous
#include <cuda_runtime.h>
#include <cuda_bf16.h>
#include <cstdint>

#define NN 10000
#define EE 320000
#define DD 256

// ---------------- scratch (static device globals; no allocation) ----------------
__device__ float g_esrc[NN * DD];
__device__ float g_edst[NN * DD];
__device__ float g_fsrc[NN * DD];
__device__ float g_agg[NN * DD];
__device__ float g_outdeg[NN];
__device__ float g_indeg[NN];
// w_edge^T split bf16 hi/lo, pre-swizzled per K32 chunk in the paired-row layout:
// 16B-unit index = c*1024 + (n>>1)*8 + (n&1)*4 + (u ^ ((n>>1)&3)),  u = k8-unit (0..3)
__device__ uint4 g_Bswhi[8 * 1024];
__device__ uint4 g_Bswlo[8 * 1024];

// ---------------- helpers ----------------
__device__ __forceinline__ uint32_t smem_to_u32(const void* p) {
    uint32_t a;
    asm("{ .reg .u64 t; cvta.to.shared.u64 t, %1; cvt.u32.u64 %0, t; }" : "=r"(a) : "l"(p));
    return a;
}
__device__ __forceinline__ void ldm_x4(uint32_t& r0, uint32_t& r1, uint32_t& r2, uint32_t& r3,
                                       uint32_t addr) {
    asm volatile("ldmatrix.sync.aligned.m8n8.x4.shared.b16 {%0,%1,%2,%3}, [%4];"
                 : "=r"(r0), "=r"(r1), "=r"(r2), "=r"(r3) : "r"(addr));
}
__device__ __forceinline__ void mma16816(float* c, const uint32_t* a, const uint32_t* b) {
    asm volatile(
        "mma.sync.aligned.m16n8k16.row.col.f32.bf16.bf16.f32 "
        "{%0,%1,%2,%3}, {%4,%5,%6,%7}, {%8,%9}, {%0,%1,%2,%3};"
        : "+f"(c[0]), "+f"(c[1]), "+f"(c[2]), "+f"(c[3])
        : "r"(a[0]), "r"(a[1]), "r"(a[2]), "r"(a[3]), "r"(b[0]), "r"(b[1]));
}
#define CP_ASYNC16(saddr, gptr) \
    asm volatile("cp.async.cg.shared.global [%0], [%1], 16;" :: "r"(saddr), "l"(gptr) : "memory")
#define CP_COMMIT() asm volatile("cp.async.commit_group;" ::: "memory")
#define CP_WAIT2()  asm volatile("cp.async.wait_group 2;" ::: "memory")
#define CP_WAIT_ALL() asm volatile("cp.async.wait_group 0;" ::: "memory")

__device__ __forceinline__ uint32_t split_pair(float a, float b, uint32_t& lo) {
    __nv_bfloat16 ha = __float2bfloat16(a), hb = __float2bfloat16(b);
    __nv_bfloat16 la = __float2bfloat16(a - __bfloat162float(ha));
    __nv_bfloat16 lb = __float2bfloat16(b - __bfloat162float(hb));
    lo = ((uint32_t)__bfloat16_as_ushort(lb) << 16) | (uint32_t)__bfloat16_as_ushort(la);
    return ((uint32_t)__bfloat16_as_ushort(hb) << 16) | (uint32_t)__bfloat16_as_ushort(ha);
}

// ---------------- launch 0: weight prep + zero (fused) ----------------
__global__ void fuse0_kernel(const float* __restrict__ w_edge) {
    int t = blockIdx.x * blockDim.x + threadIdx.x;
    if (t < NN * DD) g_agg[t] = 0.f;
    if (t < NN) { g_outdeg[t] = 0.f; g_indeg[t] = 0.f; }
    if (t < 8192) {
        int n = t & 255;
        int g = t >> 8;                 // 0..31
        int c = g >> 2, u = g & 3;      // K32 chunk, k8-unit
        uint32_t h[4], l[4];
        #pragma unroll
        for (int j = 0; j < 4; j++) {
            int k = c * 32 + u * 8 + 2 * j;
            float a = w_edge[(size_t)k * DD + n];
            float b = w_edge[(size_t)(k + 1) * DD + n];
            h[j] = split_pair(a, b, l[j]);
        }
        int di = c * 1024 + (n >> 1) * 8 + (n & 1) * 4 + (u ^ ((n >> 1) & 3));
        g_Bswhi[di] = make_uint4(h[0], h[1], h[2], h[3]);
        g_Bswlo[di] = make_uint4(l[0], l[1], l[2], l[3]);
    }
}

// ---------------- launch 1: degrees ----------------
__global__ void degree_kernel(const int* __restrict__ src, const int* __restrict__ dst) {
    int e = blockIdx.x * blockDim.x + threadIdx.x;
    if (e < EE) {
        atomicAdd(&g_outdeg[src[e]], 1.f);
        atomicAdd(&g_indeg[dst[e]], 1.f);
    }
}

// ---------------- SMEM layout for edge kernel ----------------
static constexpr int S_B   = 0;          // 4 ring slots x 16KB = 64KB
static constexpr int S_A   = 65536;      // 2 bufs x 16KB (hi 8KB + lo 8KB)
static constexpr int S_IDX = 98304;      // 128 src + 128 dst ints = 1KB
static constexpr int S_TOTAL = 99328;

// paired-row swizzled offset for a (row, k8-unit) 16B tile
__device__ __forceinline__ uint32_t prow_off(uint32_t r, uint32_t u) {
    return (r >> 1) * 128u + (r & 1) * 64u + ((u ^ ((r >> 1) & 3u)) << 4);
}

// ---------------- launch 3: edge GEMM (pipelined mma.sync bf16x3) ----------------
__global__ void __launch_bounds__(512, 1)
edge_mma_kernel(const float* __restrict__ edgef, const int* __restrict__ src,
                const int* __restrict__ dst, const float* __restrict__ b_edge,
                float* __restrict__ m_out)
{
    extern __shared__ char smem[];
    const uint32_t sb = smem_to_u32(smem);
    const int tid = threadIdx.x;
    const int lane = tid & 31;
    const int wid = tid >> 5;
    const int warp_m = wid & 3;       // 0..3 -> rows 32*warp_m
    const int warp_n = wid >> 2;      // 0..3 -> cols 64*warp_n
    const int tile = blockIdx.x;      // 128 edges

    float acc[2][8][4];
    #pragma unroll
    for (int mt = 0; mt < 2; mt++)
        #pragma unroll
        for (int nt = 0; nt < 8; nt++)
            #pragma unroll
            for (int i = 0; i < 4; i++) acc[mt][nt][i] = 0.f;

    // A convert mapping: thread -> (row, k8-unit)
    const int arow = tid >> 2;
    const int au = tid & 3;
    const float* gA = edgef + (size_t)(tile * 128 + arow) * DD + au * 8;

    // ---- prologue ----
    // B stages 0,1,2 (stage s: chunk s>>1, type s&1)
    #pragma unroll
    for (int s = 0; s < 3; s++) {
        const uint4* bsrc = ((s & 1) ? g_Bswlo : g_Bswhi) + (s >> 1) * 1024;
        #pragma unroll
        for (int i = 0; i < 2; i++) {
            int idx = tid + i * 512;
            CP_ASYNC16(sb + S_B + s * 16384 + idx * 16, bsrc + idx);
        }
        CP_COMMIT();
    }
    if (tid < 128) {
        ((int*)(smem + S_IDX))[tid] = src[tile * 128 + tid];
        ((int*)(smem + S_IDX + 512))[tid] = dst[tile * 128 + tid];
    }
    // A(0): load + convert into abuf0
    float4 rx0 = *(const float4*)(gA);
    float4 rx1 = *(const float4*)(gA + 4);
    {
        uint32_t l0, l1, l2, l3;
        uint32_t h0 = split_pair(rx0.x, rx0.y, l0);
        uint32_t h1 = split_pair(rx0.z, rx0.w, l1);
        uint32_t h2 = split_pair(rx1.x, rx1.y, l2);
        uint32_t h3 = split_pair(rx1.z, rx1.w, l3);
        uint32_t off = prow_off(arow, au);
        *(uint4*)(smem + S_A + off) = make_uint4(h0, h1, h2, h3);
        *(uint4*)(smem + S_A + 8192 + off) = make_uint4(l0, l1, l2, l3);
    }
    // prefetch A(1) into regs
    rx0 = *(const float4*)(gA + 32);
    rx1 = *(const float4*)(gA + 36);

    CP_WAIT2();          // B(0) done
    __syncthreads();

    const uint32_t a_row = (uint32_t)(lane & 15);
    const uint32_t a_kh  = (uint32_t)(lane >> 4);
    const uint32_t b_nl  = (uint32_t)((lane & 7) + ((lane >> 4) << 3));
    const uint32_t b_kh  = (uint32_t)((lane >> 3) & 1);

    // ---- mainloop: 16 stages ----
    #pragma unroll 1
    for (int s = 0; s < 16; s++) {
        const int c = s >> 1;
        const int tpe = s & 1;          // 0 = hi stage (2-term), 1 = lo stage (1-term)
        const uint32_t bbase = sb + S_B + (uint32_t)(s & 3) * 16384u;
        const uint32_t abase = sb + S_A + (uint32_t)(c & 1) * 16384u;

        // issue B(s+3) into ring slot (s+3)&3 (its last reader was stage s-1)
        if (s + 3 < 16) {
            const int s3 = s + 3;
            const uint4* bsrc = ((s3 & 1) ? g_Bswlo : g_Bswhi) + (s3 >> 1) * 1024;
            #pragma unroll
            for (int i = 0; i < 2; i++) {
                int idx = tid + i * 512;
                CP_ASYNC16(sb + S_B + (s3 & 3) * 16384 + idx * 16, bsrc + idx);
            }
            CP_COMMIT();
        } else {
            CP_COMMIT();   // empty group keeps outstanding-count invariant
        }

        // ---- MMA over 2 k16 steps of this K32 chunk ----
        #pragma unroll
        for (int ks = 0; ks < 2; ks++) {
            uint32_t ah[2][4], al[2][4];
            #pragma unroll
            for (int mt = 0; mt < 2; mt++) {
                uint32_t r = (uint32_t)(warp_m * 32 + mt * 16) + a_row;
                uint32_t u = (uint32_t)(ks * 2) + a_kh;
                uint32_t off = prow_off(r, u);
                ldm_x4(ah[mt][0], ah[mt][1], ah[mt][2], ah[mt][3], abase + off);
                if (tpe == 0)
                    ldm_x4(al[mt][0], al[mt][1], al[mt][2], al[mt][3], abase + 8192 + off);
            }
            #pragma unroll
            for (int j = 0; j < 4; j++) {
                uint32_t n = (uint32_t)(warp_n * 64 + j * 16) + b_nl;
                uint32_t u = (uint32_t)(ks * 2) + b_kh;
                uint32_t boff = prow_off(n, u);
                uint32_t bf[4];
                ldm_x4(bf[0], bf[1], bf[2], bf[3], bbase + boff);
                #pragma unroll
                for (int mt = 0; mt < 2; mt++) {
                    mma16816(acc[mt][2 * j + 0], ah[mt], bf + 0);
                    mma16816(acc[mt][2 * j + 1], ah[mt], bf + 2);
                    if (tpe == 0) {
                        mma16816(acc[mt][2 * j + 0], al[mt], bf + 0);
                        mma16816(acc[mt][2 * j + 1], al[mt], bf + 2);
                    }
                }
            }
        }

        // ---- on lo stages: convert A(c+1) into the other A buffer; prefetch A(c+2) ----
        if (tpe == 1) {
            if (c < 7) {
                uint32_t l0, l1, l2, l3;
                uint32_t h0 = split_pair(rx0.x, rx0.y, l0);
                uint32_t h1 = split_pair(rx0.z, rx0.w, l1);
                uint32_t h2 = split_pair(rx1.x, rx1.y, l2);
                uint32_t h3 = split_pair(rx1.z, rx1.w, l3);
                uint32_t dstb = sb + S_A + (uint32_t)((c + 1) & 1) * 16384u + prow_off(arow, au);
                asm volatile("st.shared.v4.b32 [%0], {%1,%2,%3,%4};"
                             :: "r"(dstb), "r"(h0), "r"(h1), "r"(h2), "r"(h3) : "memory");
                asm volatile("st.shared.v4.b32 [%0], {%1,%2,%3,%4};"
                             :: "r"(dstb + 8192), "r"(l0), "r"(l1), "r"(l2), "r"(l3) : "memory");
            }
            if (c < 6) {
                rx0 = *(const float4*)(gA + (c + 2) * 32);
                rx1 = *(const float4*)(gA + (c + 2) * 32 + 4);
            }
        }

        CP_WAIT2();        // B(s+1) complete
        __syncthreads();
    }

    // ---- epilogue: direct from fragments ----
    {
        // bias: cached per thread for its 8 n-pairs (same cols for all rows)
        float2 bb[8];
        #pragma unroll
        for (int nt = 0; nt < 8; nt++) {
            int cc = warp_n * 64 + nt * 8 + (lane & 3) * 2;
            bb[nt] = *(const float2*)(b_edge + cc);
        }
        #pragma unroll
        for (int mt = 0; mt < 2; mt++) {
            #pragma unroll
            for (int rh = 0; rh < 2; rh++) {
                int r = warp_m * 32 + mt * 16 + rh * 8 + (lane >> 2);
                int e = tile * 128 + r;
                int sN = ((const int*)(smem + S_IDX))[r];
                int dN = ((const int*)(smem + S_IDX + 512))[r];
                const float* pe1 = g_esrc + (size_t)sN * DD;
                const float* pe2 = g_edst + (size_t)dN * DD;
                const float* pf  = g_fsrc + (size_t)sN * DD;
                float* pm = m_out + (size_t)e * DD;
                float* pa = g_agg + (size_t)dN * DD;
                #pragma unroll
                for (int nt = 0; nt < 8; nt++) {
                    int cc = warp_n * 64 + nt * 8 + (lane & 3) * 2;
                    float a0 = acc[mt][nt][rh * 2 + 0];
                    float a1 = acc[mt][nt][rh * 2 + 1];
                    float2 e1 = *(const float2*)(pe1 + cc);
                    float2 e2 = *(const float2*)(pe2 + cc);
                    float2 f  = *(const float2*)(pf + cc);
                    float mx = a0 + bb[nt].x + e1.x + e2.x;
                    float my = a1 + bb[nt].y + e1.y + e2.y;
                    *(float2*)(pm + cc) = make_float2(mx, my);
                    float s0 = f.x / (1.f + __expf(-mx));
                    float s1 = f.y / (1.f + __expf(-my));
                    asm volatile("red.global.add.v2.f32 [%0], {%1,%2};"
                                 :: "l"(pa + cc), "f"(s0), "f"(s1) : "memory");
                }
            }
        }
    }
    CP_WAIT_ALL();
}

// ---- SIMT GEMM 64x64x16 for node-sized matmuls ----
// MODE 0: z=0 -> esrc (+ fsrc rows), z=1 -> edst
// MODE 3: rst = nodef + (g_agg@weight)*indeg^-1/2 + bias
template <int MODE>
__global__ void __launch_bounds__(256)
gemm_kernel(const float* __restrict__ A_in, const float* __restrict__ B0,
            const float* __restrict__ bias0, const float* __restrict__ B1,
            const float* __restrict__ bias1, float* __restrict__ C, int M,
            const float* __restrict__ nodef)
{
    const float* A = (MODE == 3) ? (const float*)g_agg : A_in;
    const float* B = (MODE == 0 && blockIdx.z) ? B1 : B0;
    const float* bias = (MODE == 0 && blockIdx.z) ? bias1 : bias0;

    constexpr int BM = 64, BN = 64, BK = 16;
    __shared__ float As[BK][BM + 1];
    __shared__ float Bs[BK][BN];

    const int tid = threadIdx.x;
    const int tx = tid & 15, ty = tid >> 4;
    const int bm0 = blockIdx.y * BM, bn0 = blockIdx.x * BN;
    const int lrow = tid >> 2, lk = (tid & 3) * 4;
    const int brow = tid >> 4, bcol = (tid & 15) * 4;

    float acc[4][4];
    #pragma unroll
    for (int i = 0; i < 4; i++)
        #pragma unroll
        for (int j = 0; j < 4; j++) acc[i][j] = 0.f;

    const int ty4 = ty * 4, tx4 = tx * 4;
    for (int k0 = 0; k0 < DD; k0 += BK) {
        float4 av;
        int ar = bm0 + lrow;
        if (ar < M) av = *(const float4*)(A + (size_t)ar * DD + k0 + lk);
        else        av = make_float4(0.f, 0.f, 0.f, 0.f);
        As[lk + 0][lrow] = av.x; As[lk + 1][lrow] = av.y;
        As[lk + 2][lrow] = av.z; As[lk + 3][lrow] = av.w;
        *(float4*)&Bs[brow][bcol] = *(const float4*)(B + (size_t)(k0 + brow) * DD + bn0 + bcol);
        __syncthreads();
        #pragma unroll
        for (int kk = 0; kk < BK; kk++) {
            float a0 = As[kk][ty4 + 0], a1 = As[kk][ty4 + 1];
            float a2 = As[kk][ty4 + 2], a3 = As[kk][ty4 + 3];
            float4 b = *(float4*)&Bs[kk][tx4];
            acc[0][0] += a0 * b.x; acc[0][1] += a0 * b.y; acc[0][2] += a0 * b.z; acc[0][3] += a0 * b.w;
            acc[1][0] += a1 * b.x; acc[1][1] += a1 * b.y; acc[1][2] += a1 * b.z; acc[1][3] += a1 * b.w;
            acc[2][0] += a2 * b.x; acc[2][1] += a2 * b.y; acc[2][2] += a2 * b.z; acc[2][3] += a2 * b.w;
            acc[3][0] += a3 * b.x; acc[3][1] += a3 * b.y; acc[3][2] += a3 * b.z; acc[3][3] += a3 * b.w;
        }
        __syncthreads();
    }

    const float4 bb = *(const float4*)(bias + bn0 + tx4);
    const size_t coloff = (size_t)(bn0 + tx4);
    #pragma unroll
    for (int i = 0; i < 4; i++) {
        int r = bm0 + ty4 + i;
        if (r >= M) continue;
        if (MODE == 0) {
            float4 o;
            o.x = acc[i][0] + bb.x; o.y = acc[i][1] + bb.y;
            o.z = acc[i][2] + bb.z; o.w = acc[i][3] + bb.w;
            float* dstp = blockIdx.z ? g_edst : g_esrc;
            *(float4*)(dstp + (size_t)r * DD + coloff) = o;
            if (blockIdx.z == 0) {
                float nrm = rsqrtf(fmaxf(g_outdeg[r], 1.f));
                const float4 nf = *(const float4*)(nodef + (size_t)r * DD + coloff);
                float4 fo;
                fo.x = nf.x * nrm; fo.y = nf.y * nrm;
                fo.z = nf.z * nrm; fo.w = nf.w * nrm;
                *(float4*)(g_fsrc + (size_t)r * DD + coloff) = fo;
            }
        } else {
            float nrm = rsqrtf(fmaxf(g_indeg[r], 1.f));
            const float4 nf = *(const float4*)(nodef + (size_t)r * DD + coloff);
            float4 o;
            o.x = nf.x + acc[i][0] * nrm + bb.x;
            o.y = nf.y + acc[i][1] * nrm + bb.y;
            o.z = nf.z + acc[i][2] * nrm + bb.z;
            o.w = nf.w + acc[i][3] * nrm + bb.w;
            *(float4*)(C + (size_t)r * DD + coloff) = o;
        }
    }
}

extern "C" void kernel_launch(void* const* d_in, const int* in_sizes, int n_in,
                              void* d_out, int out_size) {
    const float* nodef  = (const float*)d_in[0];
    const float* edgef  = (const float*)d_in[1];
    const int*   src    = (const int*)d_in[2];
    const int*   dst    = (const int*)d_in[3];
    const float* weight = (const float*)d_in[4];
    const float* bias   = (const float*)d_in[5];
    const float* w_src  = (const float*)d_in[6];
    const float* b_src  = (const float*)d_in[7];
    const float* w_dst  = (const float*)d_in[8];
    const float* b_dst  = (const float*)d_in[9];
    const float* w_edge = (const float*)d_in[10];
    const float* b_edge = (const float*)d_in[11];

    float* rst   = (float*)d_out;             // [N, D]
    float* m_out = rst + (size_t)NN * DD;     // [E, D]

    static bool attr_set = false;
    if (!attr_set) {
        cudaFuncSetAttribute(edge_mma_kernel, cudaFuncAttributeMaxDynamicSharedMemorySize, S_TOTAL);
        attr_set = true;
    }

    // launch 0: weight prep + zero
    fuse0_kernel<<<(NN * DD + 255) / 256, 256>>>(w_edge);
    // launch 1: degrees
    degree_kernel<<<(EE + 255) / 256, 256>>>(src, dst);
    // launch 2: e_src (+fsrc) / e_dst
    {
        dim3 g(DD / 64, (NN + 63) / 64, 2);
        gemm_kernel<0><<<g, 256>>>(nodef, w_src, b_src, w_dst, b_dst, nullptr, NN, nodef);
    }
    // launch 3 (profiled): edge GEMM + fused epilogue
    edge_mma_kernel<<<EE / 128, 512, S_TOTAL>>>(edgef, src, dst, b_edge, m_out);
    // launch 4: final projection + norm + bias + residual
    {
        dim3 g(DD / 64, (NN + 63) / 64, 1);
        gemm_kernel<3><<<g, 256>>>(nullptr, weight, bias, nullptr, nullptr, rst, NN, nodef);
    }
}

// round 9
// speedup vs baseline: 1.4700x; 1.1619x over previous
#include <cuda_runtime.h>
#include <cuda_bf16.h>
#include <cstdint>

#define NN 10000
#define EE 320000
#define DD 256

// ---------------- scratch (static device globals; no allocation) ----------------
__device__ float g_esrc[NN * DD];
__device__ float g_edst[NN * DD];
__device__ float g_fsrc[NN * DD];
__device__ float g_agg[NN * DD];
__device__ float g_outdeg[NN];
__device__ float g_indeg[NN];
// w_edge^T split bf16 hi/lo, pre-swizzled per K32 chunk in the paired-row layout:
// 16B-unit index = c*1024 + (n>>1)*8 + (n&1)*4 + (u ^ ((n>>1)&3)),  u = k8-unit (0..3)
__device__ uint4 g_Bswhi[8 * 1024];
__device__ uint4 g_Bswlo[8 * 1024];

// ---------------- helpers ----------------
__device__ __forceinline__ uint32_t smem_to_u32(const void* p) {
    uint32_t a;
    asm("{ .reg .u64 t; cvta.to.shared.u64 t, %1; cvt.u32.u64 %0, t; }" : "=r"(a) : "l"(p));
    return a;
}
__device__ __forceinline__ void ldm_x4(uint32_t& r0, uint32_t& r1, uint32_t& r2, uint32_t& r3,
                                       uint32_t addr) {
    asm volatile("ldmatrix.sync.aligned.m8n8.x4.shared.b16 {%0,%1,%2,%3}, [%4];"
                 : "=r"(r0), "=r"(r1), "=r"(r2), "=r"(r3) : "r"(addr));
}
__device__ __forceinline__ void mma16816(float* c, const uint32_t* a, const uint32_t* b) {
    asm volatile(
        "mma.sync.aligned.m16n8k16.row.col.f32.bf16.bf16.f32 "
        "{%0,%1,%2,%3}, {%4,%5,%6,%7}, {%8,%9}, {%0,%1,%2,%3};"
        : "+f"(c[0]), "+f"(c[1]), "+f"(c[2]), "+f"(c[3])
        : "r"(a[0]), "r"(a[1]), "r"(a[2]), "r"(a[3]), "r"(b[0]), "r"(b[1]));
}
#define CP_ASYNC16(saddr, gptr) \
    asm volatile("cp.async.cg.shared.global [%0], [%1], 16;" :: "r"(saddr), "l"(gptr) : "memory")
#define CP_COMMIT() asm volatile("cp.async.commit_group;" ::: "memory")
#define CP_WAIT2()  asm volatile("cp.async.wait_group 2;" ::: "memory")
#define CP_WAIT_ALL() asm volatile("cp.async.wait_group 0;" ::: "memory")

__device__ __forceinline__ uint32_t split_pair(float a, float b, uint32_t& lo) {
    __nv_bfloat16 ha = __float2bfloat16(a), hb = __float2bfloat16(b);
    __nv_bfloat16 la = __float2bfloat16(a - __bfloat162float(ha));
    __nv_bfloat16 lb = __float2bfloat16(b - __bfloat162float(hb));
    lo = ((uint32_t)__bfloat16_as_ushort(lb) << 16) | (uint32_t)__bfloat16_as_ushort(la);
    return ((uint32_t)__bfloat16_as_ushort(hb) << 16) | (uint32_t)__bfloat16_as_ushort(ha);
}

// ---------------- launch 0: weight prep + zero (fused) ----------------
__global__ void fuse0_kernel(const float* __restrict__ w_edge) {
    int t = blockIdx.x * blockDim.x + threadIdx.x;
    if (t < NN * DD) g_agg[t] = 0.f;
    if (t < NN) { g_outdeg[t] = 0.f; g_indeg[t] = 0.f; }
    if (t < 8192) {
        int n = t & 255;
        int g = t >> 8;                 // 0..31
        int c = g >> 2, u = g & 3;      // K32 chunk, k8-unit
        uint32_t h[4], l[4];
        #pragma unroll
        for (int j = 0; j < 4; j++) {
            int k = c * 32 + u * 8 + 2 * j;
            float a = w_edge[(size_t)k * DD + n];
            float b = w_edge[(size_t)(k + 1) * DD + n];
            h[j] = split_pair(a, b, l[j]);
        }
        int di = c * 1024 + (n >> 1) * 8 + (n & 1) * 4 + (u ^ ((n >> 1) & 3));
        g_Bswhi[di] = make_uint4(h[0], h[1], h[2], h[3]);
        g_Bswlo[di] = make_uint4(l[0], l[1], l[2], l[3]);
    }
}

// ---------------- launch 1: degrees ----------------
__global__ void degree_kernel(const int* __restrict__ src, const int* __restrict__ dst) {
    int e = blockIdx.x * blockDim.x + threadIdx.x;
    if (e < EE) {
        atomicAdd(&g_outdeg[src[e]], 1.f);
        atomicAdd(&g_indeg[dst[e]], 1.f);
    }
}

// ---------------- SMEM layout for edge kernel ----------------
// B ring: 4 slots x 32KB (hi 16KB @ +0, lo 16KB @ +16384) = 128KB
static constexpr int S_B   = 0;
static constexpr int S_A   = 131072;     // 2 bufs x 16KB (hi 8KB + lo 8KB) = 32KB
static constexpr int S_IDX = 163840;     // 128 src + 128 dst ints = 1KB
static constexpr int S_TOTAL = 164864;

// paired-row swizzled offset for a (row, k8-unit) 16B tile
__device__ __forceinline__ uint32_t prow_off(uint32_t r, uint32_t u) {
    return (r >> 1) * 128u + (r & 1) * 64u + ((u ^ ((r >> 1) & 3u)) << 4);
}

// ---------------- launch 3: edge GEMM (8-stage pipelined mma.sync bf16x3) ----------------
__global__ void __launch_bounds__(512, 1)
edge_mma_kernel(const float* __restrict__ edgef, const int* __restrict__ src,
                const int* __restrict__ dst, const float* __restrict__ b_edge,
                float* __restrict__ m_out)
{
    extern __shared__ char smem[];
    const uint32_t sb = smem_to_u32(smem);
    const int tid = threadIdx.x;
    const int lane = tid & 31;
    const int wid = tid >> 5;
    const int warp_m = wid & 3;       // rows 32*warp_m
    const int warp_n = wid >> 2;      // cols 64*warp_n
    const int tile = blockIdx.x;      // 128 edges

    float acc[2][8][4];
    #pragma unroll
    for (int mt = 0; mt < 2; mt++)
        #pragma unroll
        for (int nt = 0; nt < 8; nt++)
            #pragma unroll
            for (int i = 0; i < 4; i++) acc[mt][nt][i] = 0.f;

    // A convert mapping: thread -> (row, k8-unit)
    const int arow = tid >> 2;
    const int au = tid & 3;
    const float* gA = edgef + (size_t)(tile * 128 + arow) * DD + au * 8;

    // ---- prologue: B chunks 0,1,2 into ring slots 0,1,2 ----
    #pragma unroll
    for (int c = 0; c < 3; c++) {
        const uint4* bh = g_Bswhi + c * 1024;
        const uint4* bl = g_Bswlo + c * 1024;
        #pragma unroll
        for (int i = 0; i < 2; i++) {
            int idx = tid + i * 512;
            CP_ASYNC16(sb + S_B + c * 32768 + idx * 16,         bh + idx);
            CP_ASYNC16(sb + S_B + c * 32768 + 16384 + idx * 16, bl + idx);
        }
        CP_COMMIT();
    }
    if (tid < 128) {
        ((int*)(smem + S_IDX))[tid] = src[tile * 128 + tid];
        ((int*)(smem + S_IDX + 512))[tid] = dst[tile * 128 + tid];
    }
    // A(0): load + convert into Abuf0
    float4 rx0 = *(const float4*)(gA);
    float4 rx1 = *(const float4*)(gA + 4);
    {
        uint32_t l0, l1, l2, l3;
        uint32_t h0 = split_pair(rx0.x, rx0.y, l0);
        uint32_t h1 = split_pair(rx0.z, rx0.w, l1);
        uint32_t h2 = split_pair(rx1.x, rx1.y, l2);
        uint32_t h3 = split_pair(rx1.z, rx1.w, l3);
        uint32_t off = prow_off(arow, au);
        *(uint4*)(smem + S_A + off) = make_uint4(h0, h1, h2, h3);
        *(uint4*)(smem + S_A + 8192 + off) = make_uint4(l0, l1, l2, l3);
    }
    // prefetch A(1) into regs
    rx0 = *(const float4*)(gA + 32);
    rx1 = *(const float4*)(gA + 36);

    CP_WAIT2();          // B(0) done (slots 1,2 may be in flight)
    __syncthreads();

    const uint32_t a_row = (uint32_t)(lane & 15);
    const uint32_t a_kh  = (uint32_t)(lane >> 4);
    const uint32_t b_nl  = (uint32_t)((lane & 7) + ((lane >> 4) << 3));
    const uint32_t b_kh  = (uint32_t)((lane >> 3) & 1);

    // ---- mainloop: 8 stages (one K32 chunk each, all 3 terms) ----
    #pragma unroll 1
    for (int s = 0; s < 8; s++) {
        const uint32_t bbase = sb + S_B + (uint32_t)(s & 3) * 32768u;
        const uint32_t abase = sb + S_A + (uint32_t)(s & 1) * 16384u;

        // issue B(s+3) into ring slot (s+3)&3 — disjoint from slots s, s+1, s+2;
        // its last reader (stage s-1) is behind the end-of-stage barrier.
        if (s + 3 < 8) {
            const int c3 = s + 3;
            const uint4* bh = g_Bswhi + c3 * 1024;
            const uint4* bl = g_Bswlo + c3 * 1024;
            const uint32_t slot = sb + S_B + (uint32_t)(c3 & 3) * 32768u;
            #pragma unroll
            for (int i = 0; i < 2; i++) {
                int idx = tid + i * 512;
                CP_ASYNC16(slot + idx * 16,         bh + idx);
                CP_ASYNC16(slot + 16384 + idx * 16, bl + idx);
            }
            CP_COMMIT();
        } else {
            CP_COMMIT();   // empty group keeps wait-count invariant
        }

        // ---- MMA: 2 k16 steps, 3 terms each ----
        #pragma unroll
        for (int ks = 0; ks < 2; ks++) {
            uint32_t ah[2][4], al[2][4];
            #pragma unroll
            for (int mt = 0; mt < 2; mt++) {
                uint32_t r = (uint32_t)(warp_m * 32 + mt * 16) + a_row;
                uint32_t u = (uint32_t)(ks * 2) + a_kh;
                uint32_t off = prow_off(r, u);
                ldm_x4(ah[mt][0], ah[mt][1], ah[mt][2], ah[mt][3], abase + off);
                ldm_x4(al[mt][0], al[mt][1], al[mt][2], al[mt][3], abase + 8192 + off);
            }
            #pragma unroll
            for (int j = 0; j < 4; j++) {
                uint32_t n = (uint32_t)(warp_n * 64 + j * 16) + b_nl;
                uint32_t u = (uint32_t)(ks * 2) + b_kh;
                uint32_t boff = prow_off(n, u);
                uint32_t bh[4], bl[4];
                ldm_x4(bh[0], bh[1], bh[2], bh[3], bbase + boff);
                ldm_x4(bl[0], bl[1], bl[2], bl[3], bbase + 16384 + boff);
                #pragma unroll
                for (int mt = 0; mt < 2; mt++) {
                    mma16816(acc[mt][2 * j + 0], ah[mt], bh + 0);
                    mma16816(acc[mt][2 * j + 1], ah[mt], bh + 2);
                    mma16816(acc[mt][2 * j + 0], al[mt], bh + 0);
                    mma16816(acc[mt][2 * j + 1], al[mt], bh + 2);
                    mma16816(acc[mt][2 * j + 0], ah[mt], bl + 0);
                    mma16816(acc[mt][2 * j + 1], ah[mt], bl + 2);
                }
            }
        }

        // ---- convert A(s+1); prefetch A(s+2) ----
        if (s < 7) {
            uint32_t l0, l1, l2, l3;
            uint32_t h0 = split_pair(rx0.x, rx0.y, l0);
            uint32_t h1 = split_pair(rx0.z, rx0.w, l1);
            uint32_t h2 = split_pair(rx1.x, rx1.y, l2);
            uint32_t h3 = split_pair(rx1.z, rx1.w, l3);
            uint32_t dstb = sb + S_A + (uint32_t)((s + 1) & 1) * 16384u + prow_off(arow, au);
            asm volatile("st.shared.v4.b32 [%0], {%1,%2,%3,%4};"
                         :: "r"(dstb), "r"(h0), "r"(h1), "r"(h2), "r"(h3) : "memory");
            asm volatile("st.shared.v4.b32 [%0], {%1,%2,%3,%4};"
                         :: "r"(dstb + 8192), "r"(l0), "r"(l1), "r"(l2), "r"(l3) : "memory");
            if (s < 6) {
                rx0 = *(const float4*)(gA + (s + 2) * 32);
                rx1 = *(const float4*)(gA + (s + 2) * 32 + 4);
            }
            CP_WAIT2();        // B(s+1) complete
            __syncthreads();
        }
        // s == 7: fall straight into epilogue (no wait, no barrier)
    }

    // ---- epilogue: direct from fragments ----
    {
        float2 bb[8];
        #pragma unroll
        for (int nt = 0; nt < 8; nt++) {
            int cc = warp_n * 64 + nt * 8 + (lane & 3) * 2;
            bb[nt] = *(const float2*)(b_edge + cc);
        }
        #pragma unroll
        for (int mt = 0; mt < 2; mt++) {
            #pragma unroll
            for (int rh = 0; rh < 2; rh++) {
                int r = warp_m * 32 + mt * 16 + rh * 8 + (lane >> 2);
                int e = tile * 128 + r;
                int sN = ((const int*)(smem + S_IDX))[r];
                int dN = ((const int*)(smem + S_IDX + 512))[r];
                const float* pe1 = g_esrc + (size_t)sN * DD;
                const float* pe2 = g_edst + (size_t)dN * DD;
                const float* pf  = g_fsrc + (size_t)sN * DD;
                float* pm = m_out + (size_t)e * DD;
                float* pa = g_agg + (size_t)dN * DD;
                #pragma unroll
                for (int nt = 0; nt < 8; nt++) {
                    int cc = warp_n * 64 + nt * 8 + (lane & 3) * 2;
                    float a0 = acc[mt][nt][rh * 2 + 0];
                    float a1 = acc[mt][nt][rh * 2 + 1];
                    float2 e1 = *(const float2*)(pe1 + cc);
                    float2 e2 = *(const float2*)(pe2 + cc);
                    float2 f  = *(const float2*)(pf + cc);
                    float mx = a0 + bb[nt].x + e1.x + e2.x;
                    float my = a1 + bb[nt].y + e1.y + e2.y;
                    *(float2*)(pm + cc) = make_float2(mx, my);
                    float s0 = f.x / (1.f + __expf(-mx));
                    float s1 = f.y / (1.f + __expf(-my));
                    asm volatile("red.global.add.v2.f32 [%0], {%1,%2};"
                                 :: "l"(pa + cc), "f"(s0), "f"(s1) : "memory");
                }
            }
        }
    }
    CP_WAIT_ALL();
}

// ---- SIMT GEMM 64x64x16 for node-sized matmuls ----
// MODE 0: z=0 -> esrc (+ fsrc rows), z=1 -> edst
// MODE 3: rst = nodef + (g_agg@weight)*indeg^-1/2 + bias
template <int MODE>
__global__ void __launch_bounds__(256)
gemm_kernel(const float* __restrict__ A_in, const float* __restrict__ B0,
            const float* __restrict__ bias0, const float* __restrict__ B1,
            const float* __restrict__ bias1, float* __restrict__ C, int M,
            const float* __restrict__ nodef)
{
    const float* A = (MODE == 3) ? (const float*)g_agg : A_in;
    const float* B = (MODE == 0 && blockIdx.z) ? B1 : B0;
    const float* bias = (MODE == 0 && blockIdx.z) ? bias1 : bias0;

    constexpr int BM = 64, BN = 64, BK = 16;
    __shared__ float As[BK][BM + 1];
    __shared__ float Bs[BK][BN];

    const int tid = threadIdx.x;
    const int tx = tid & 15, ty = tid >> 4;
    const int bm0 = blockIdx.y * BM, bn0 = blockIdx.x * BN;
    const int lrow = tid >> 2, lk = (tid & 3) * 4;
    const int brow = tid >> 4, bcol = (tid & 15) * 4;

    float acc[4][4];
    #pragma unroll
    for (int i = 0; i < 4; i++)
        #pragma unroll
        for (int j = 0; j < 4; j++) acc[i][j] = 0.f;

    const int ty4 = ty * 4, tx4 = tx * 4;
    for (int k0 = 0; k0 < DD; k0 += BK) {
        float4 av;
        int ar = bm0 + lrow;
        if (ar < M) av = *(const float4*)(A + (size_t)ar * DD + k0 + lk);
        else        av = make_float4(0.f, 0.f, 0.f, 0.f);
        As[lk + 0][lrow] = av.x; As[lk + 1][lrow] = av.y;
        As[lk + 2][lrow] = av.z; As[lk + 3][lrow] = av.w;
        *(float4*)&Bs[brow][bcol] = *(const float4*)(B + (size_t)(k0 + brow) * DD + bn0 + bcol);
        __syncthreads();
        #pragma unroll
        for (int kk = 0; kk < BK; kk++) {
            float a0 = As[kk][ty4 + 0], a1 = As[kk][ty4 + 1];
            float a2 = As[kk][ty4 + 2], a3 = As[kk][ty4 + 3];
            float4 b = *(float4*)&Bs[kk][tx4];
            acc[0][0] += a0 * b.x; acc[0][1] += a0 * b.y; acc[0][2] += a0 * b.z; acc[0][3] += a0 * b.w;
            acc[1][0] += a1 * b.x; acc[1][1] += a1 * b.y; acc[1][2] += a1 * b.z; acc[1][3] += a1 * b.w;
            acc[2][0] += a2 * b.x; acc[2][1] += a2 * b.y; acc[2][2] += a2 * b.z; acc[2][3] += a2 * b.w;
            acc[3][0] += a3 * b.x; acc[3][1] += a3 * b.y; acc[3][2] += a3 * b.z; acc[3][3] += a3 * b.w;
        }
        __syncthreads();
    }

    const float4 bb = *(const float4*)(bias + bn0 + tx4);
    const size_t coloff = (size_t)(bn0 + tx4);
    #pragma unroll
    for (int i = 0; i < 4; i++) {
        int r = bm0 + ty4 + i;
        if (r >= M) continue;
        if (MODE == 0) {
            float4 o;
            o.x = acc[i][0] + bb.x; o.y = acc[i][1] + bb.y;
            o.z = acc[i][2] + bb.z; o.w = acc[i][3] + bb.w;
            float* dstp = blockIdx.z ? g_edst : g_esrc;
            *(float4*)(dstp + (size_t)r * DD + coloff) = o;
            if (blockIdx.z == 0) {
                float nrm = rsqrtf(fmaxf(g_outdeg[r], 1.f));
                const float4 nf = *(const float4*)(nodef + (size_t)r * DD + coloff);
                float4 fo;
                fo.x = nf.x * nrm; fo.y = nf.y * nrm;
                fo.z = nf.z * nrm; fo.w = nf.w * nrm;
                *(float4*)(g_fsrc + (size_t)r * DD + coloff) = fo;
            }
        } else {
            float nrm = rsqrtf(fmaxf(g_indeg[r], 1.f));
            const float4 nf = *(const float4*)(nodef + (size_t)r * DD + coloff);
            float4 o;
            o.x = nf.x + acc[i][0] * nrm + bb.x;
            o.y = nf.y + acc[i][1] * nrm + bb.y;
            o.z = nf.z + acc[i][2] * nrm + bb.z;
            o.w = nf.w + acc[i][3] * nrm + bb.w;
            *(float4*)(C + (size_t)r * DD + coloff) = o;
        }
    }
}

extern "C" void kernel_launch(void* const* d_in, const int* in_sizes, int n_in,
                              void* d_out, int out_size) {
    const float* nodef  = (const float*)d_in[0];
    const float* edgef  = (const float*)d_in[1];
    const int*   src    = (const int*)d_in[2];
    const int*   dst    = (const int*)d_in[3];
    const float* weight = (const float*)d_in[4];
    const float* bias   = (const float*)d_in[5];
    const float* w_src  = (const float*)d_in[6];
    const float* b_src  = (const float*)d_in[7];
    const float* w_dst  = (const float*)d_in[8];
    const float* b_dst  = (const float*)d_in[9];
    const float* w_edge = (const float*)d_in[10];
    const float* b_edge = (const float*)d_in[11];

    float* rst   = (float*)d_out;             // [N, D]
    float* m_out = rst + (size_t)NN * DD;     // [E, D]

    static bool attr_set = false;
    if (!attr_set) {
        cudaFuncSetAttribute(edge_mma_kernel, cudaFuncAttributeMaxDynamicSharedMemorySize, S_TOTAL);
        attr_set = true;
    }

    // launch 0: weight prep + zero
    fuse0_kernel<<<(NN * DD + 255) / 256, 256>>>(w_edge);
    // launch 1: degrees
    degree_kernel<<<(EE + 255) / 256, 256>>>(src, dst);
    // launch 2: e_src (+fsrc) / e_dst
    {
        dim3 g(DD / 64, (NN + 63) / 64, 2);
        gemm_kernel<0><<<g, 256>>>(nodef, w_src, b_src, w_dst, b_dst, nullptr, NN, nodef);
    }
    // launch 3 (profiled): edge GEMM + fused epilogue
    edge_mma_kernel<<<EE / 128, 512, S_TOTAL>>>(edgef, src, dst, b_edge, m_out);
    // launch 4: final projection + norm + bias + residual
    {
        dim3 g(DD / 64, (NN + 63) / 64, 1);
        gemm_kernel<3><<<g, 256>>>(nullptr, weight, bias, nullptr, nullptr, rst, NN, nodef);
    }
}

// round 10
// speedup vs baseline: 1.6634x; 1.1316x over previous
#include <cuda_runtime.h>
#include <cuda_bf16.h>
#include <cstdint>

#define NN 10000
#define EE 320000
#define DD 256

// ---------------- scratch (static device globals; no allocation) ----------------
__device__ float g_esrc[NN * DD];
__device__ float g_edst[NN * DD];
__device__ float g_fsrc[NN * DD];
__device__ float g_agg[NN * DD];
__device__ float g_outdeg[NN];
__device__ float g_indeg[NN];
// w_edge^T split bf16 hi/lo, pre-swizzled per K32 chunk in the paired-row layout:
// 16B-unit index = c*1024 + (n>>1)*8 + (n&1)*4 + (u ^ ((n>>1)&3)),  u = k8-unit (0..3)
__device__ uint4 g_Bswhi[8 * 1024];
__device__ uint4 g_Bswlo[8 * 1024];

// ---------------- helpers ----------------
__device__ __forceinline__ uint32_t smem_to_u32(const void* p) {
    uint32_t a;
    asm("{ .reg .u64 t; cvta.to.shared.u64 t, %1; cvt.u32.u64 %0, t; }" : "=r"(a) : "l"(p));
    return a;
}
__device__ __forceinline__ void ldm_x4(uint32_t& r0, uint32_t& r1, uint32_t& r2, uint32_t& r3,
                                       uint32_t addr) {
    asm volatile("ldmatrix.sync.aligned.m8n8.x4.shared.b16 {%0,%1,%2,%3}, [%4];"
                 : "=r"(r0), "=r"(r1), "=r"(r2), "=r"(r3) : "r"(addr));
}
__device__ __forceinline__ void mma16816(float* c, const uint32_t* a, const uint32_t* b) {
    asm volatile(
        "mma.sync.aligned.m16n8k16.row.col.f32.bf16.bf16.f32 "
        "{%0,%1,%2,%3}, {%4,%5,%6,%7}, {%8,%9}, {%0,%1,%2,%3};"
        : "+f"(c[0]), "+f"(c[1]), "+f"(c[2]), "+f"(c[3])
        : "r"(a[0]), "r"(a[1]), "r"(a[2]), "r"(a[3]), "r"(b[0]), "r"(b[1]));
}
#define CP_ASYNC16(saddr, gptr) \
    asm volatile("cp.async.cg.shared.global [%0], [%1], 16;" :: "r"(saddr), "l"(gptr) : "memory")
#define CP_COMMIT() asm volatile("cp.async.commit_group;" ::: "memory")
#define CP_WAIT_ALL() asm volatile("cp.async.wait_group 0;" ::: "memory")

__device__ __forceinline__ uint32_t split_pair(float a, float b, uint32_t& lo) {
    __nv_bfloat16 ha = __float2bfloat16(a), hb = __float2bfloat16(b);
    __nv_bfloat16 la = __float2bfloat16(a - __bfloat162float(ha));
    __nv_bfloat16 lb = __float2bfloat16(b - __bfloat162float(hb));
    lo = ((uint32_t)__bfloat16_as_ushort(lb) << 16) | (uint32_t)__bfloat16_as_ushort(la);
    return ((uint32_t)__bfloat16_as_ushort(hb) << 16) | (uint32_t)__bfloat16_as_ushort(ha);
}

// ---------------- launch 0: weight prep + zero (fused) ----------------
__global__ void fuse0_kernel(const float* __restrict__ w_edge) {
    int t = blockIdx.x * blockDim.x + threadIdx.x;
    if (t < NN * DD) g_agg[t] = 0.f;
    if (t < NN) { g_outdeg[t] = 0.f; g_indeg[t] = 0.f; }
    if (t < 8192) {
        int n = t & 255;
        int g = t >> 8;                 // 0..31
        int c = g >> 2, u = g & 3;      // K32 chunk, k8-unit
        uint32_t h[4], l[4];
        #pragma unroll
        for (int j = 0; j < 4; j++) {
            int k = c * 32 + u * 8 + 2 * j;
            float a = w_edge[(size_t)k * DD + n];
            float b = w_edge[(size_t)(k + 1) * DD + n];
            h[j] = split_pair(a, b, l[j]);
        }
        int di = c * 1024 + (n >> 1) * 8 + (n & 1) * 4 + (u ^ ((n >> 1) & 3));
        g_Bswhi[di] = make_uint4(h[0], h[1], h[2], h[3]);
        g_Bswlo[di] = make_uint4(l[0], l[1], l[2], l[3]);
    }
}

// ---------------- launch 1: degrees ----------------
__global__ void degree_kernel(const int* __restrict__ src, const int* __restrict__ dst) {
    int e = blockIdx.x * blockDim.x + threadIdx.x;
    if (e < EE) {
        atomicAdd(&g_outdeg[src[e]], 1.f);
        atomicAdd(&g_indeg[dst[e]], 1.f);
    }
}

// ---------------- SMEM layout for edge kernel (per CTA) ----------------
// B ring: 2 slots x 32KB (hi 16KB @ +0, lo 16KB @ +16384) = 64KB
static constexpr int S_B   = 0;
static constexpr int S_A   = 65536;      // 2 bufs x 8KB (hi 4KB + lo 4KB) = 16KB
static constexpr int S_IDX = 81920;      // 64 src + 64 dst ints = 512B
static constexpr int S_TOTAL = 82432;    // ~81KB -> 2 CTAs/SM

// paired-row swizzled offset for a (row, k8-unit) 16B tile
__device__ __forceinline__ uint32_t prow_off(uint32_t r, uint32_t u) {
    return (r >> 1) * 128u + (r & 1) * 64u + ((u ^ ((r >> 1) & 3u)) << 4);
}

// ---------------- launch 3: edge GEMM (256 threads, 2 CTAs/SM, bf16x3) ----------------
__global__ void __launch_bounds__(256, 2)
edge_mma_kernel(const float* __restrict__ edgef, const int* __restrict__ src,
                const int* __restrict__ dst, const float* __restrict__ b_edge,
                float* __restrict__ m_out)
{
    extern __shared__ char smem[];
    const uint32_t sb = smem_to_u32(smem);
    const int tid = threadIdx.x;
    const int lane = tid & 31;
    const int wid = tid >> 5;
    const int warp_m = wid & 1;       // rows 32*warp_m (64-edge tile)
    const int warp_n = wid >> 1;      // cols 64*warp_n
    const int tile = blockIdx.x;      // 64 edges

    float acc[2][8][4];
    #pragma unroll
    for (int mt = 0; mt < 2; mt++)
        #pragma unroll
        for (int nt = 0; nt < 8; nt++)
            #pragma unroll
            for (int i = 0; i < 4; i++) acc[mt][nt][i] = 0.f;

    // A mapping: thread -> (row, k8-unit); 64 rows x 4 units = 256 threads
    const int arow = tid >> 2;
    const int au = tid & 3;
    const float* gA = edgef + (size_t)(tile * 64 + arow) * DD + au * 8;

    // ---- prologue ----
    // B chunk 0 into slot 0
    {
        const uint4* bh = g_Bswhi;
        const uint4* bl = g_Bswlo;
        #pragma unroll
        for (int i = 0; i < 4; i++) {
            int idx = tid + i * 256;     // 0..1023
            CP_ASYNC16(sb + S_B + idx * 16,         bh + idx);
            CP_ASYNC16(sb + S_B + 16384 + idx * 16, bl + idx);
        }
        CP_COMMIT();
    }
    if (tid < 64) {
        ((int*)(smem + S_IDX))[tid] = src[tile * 64 + tid];
        ((int*)(smem + S_IDX + 256))[tid] = dst[tile * 64 + tid];
    }
    // A(0): load + convert into Abuf0
    float4 rx0 = *(const float4*)(gA);
    float4 rx1 = *(const float4*)(gA + 4);
    {
        uint32_t l0, l1, l2, l3;
        uint32_t h0 = split_pair(rx0.x, rx0.y, l0);
        uint32_t h1 = split_pair(rx0.z, rx0.w, l1);
        uint32_t h2 = split_pair(rx1.x, rx1.y, l2);
        uint32_t h3 = split_pair(rx1.z, rx1.w, l3);
        uint32_t off = prow_off(arow, au);
        *(uint4*)(smem + S_A + off) = make_uint4(h0, h1, h2, h3);
        *(uint4*)(smem + S_A + 4096 + off) = make_uint4(l0, l1, l2, l3);
    }
    // prefetch A(1) into regs
    rx0 = *(const float4*)(gA + 32);
    rx1 = *(const float4*)(gA + 36);

    CP_WAIT_ALL();       // B(0) done
    __syncthreads();

    const uint32_t a_row = (uint32_t)(lane & 15);
    const uint32_t a_kh  = (uint32_t)(lane >> 4);
    const uint32_t b_nl  = (uint32_t)((lane & 7) + ((lane >> 4) << 3));
    const uint32_t b_kh  = (uint32_t)((lane >> 3) & 1);

    // ---- mainloop: 8 stages (one K32 chunk each, 3 split terms) ----
    #pragma unroll 1
    for (int s = 0; s < 8; s++) {
        const uint32_t bbase = sb + S_B + (uint32_t)(s & 1) * 32768u;
        const uint32_t abase = sb + S_A + (uint32_t)(s & 1) * 8192u;

        // issue B(s+1) into slot (s+1)&1 — last read in stage s-1, behind barrier
        if (s < 7) {
            const uint4* bh = g_Bswhi + (s + 1) * 1024;
            const uint4* bl = g_Bswlo + (s + 1) * 1024;
            const uint32_t slot = sb + S_B + (uint32_t)((s + 1) & 1) * 32768u;
            #pragma unroll
            for (int i = 0; i < 4; i++) {
                int idx = tid + i * 256;
                CP_ASYNC16(slot + idx * 16,         bh + idx);
                CP_ASYNC16(slot + 16384 + idx * 16, bl + idx);
            }
            CP_COMMIT();
        }

        // ---- MMA: 2 k16 steps, 3 terms each ----
        #pragma unroll
        for (int ks = 0; ks < 2; ks++) {
            uint32_t ah[2][4], al[2][4];
            #pragma unroll
            for (int mt = 0; mt < 2; mt++) {
                uint32_t r = (uint32_t)(warp_m * 32 + mt * 16) + a_row;
                uint32_t u = (uint32_t)(ks * 2) + a_kh;
                uint32_t off = prow_off(r, u);
                ldm_x4(ah[mt][0], ah[mt][1], ah[mt][2], ah[mt][3], abase + off);
                ldm_x4(al[mt][0], al[mt][1], al[mt][2], al[mt][3], abase + 4096 + off);
            }
            #pragma unroll
            for (int j = 0; j < 4; j++) {
                uint32_t n = (uint32_t)(warp_n * 64 + j * 16) + b_nl;
                uint32_t u = (uint32_t)(ks * 2) + b_kh;
                uint32_t boff = prow_off(n, u);
                uint32_t bh[4], bl[4];
                ldm_x4(bh[0], bh[1], bh[2], bh[3], bbase + boff);
                ldm_x4(bl[0], bl[1], bl[2], bl[3], bbase + 16384 + boff);
                #pragma unroll
                for (int mt = 0; mt < 2; mt++) {
                    mma16816(acc[mt][2 * j + 0], ah[mt], bh + 0);
                    mma16816(acc[mt][2 * j + 1], ah[mt], bh + 2);
                    mma16816(acc[mt][2 * j + 0], al[mt], bh + 0);
                    mma16816(acc[mt][2 * j + 1], al[mt], bh + 2);
                    mma16816(acc[mt][2 * j + 0], ah[mt], bl + 0);
                    mma16816(acc[mt][2 * j + 1], ah[mt], bl + 2);
                }
            }
        }

        // ---- convert A(s+1) into other A buffer; prefetch A(s+2) ----
        if (s < 7) {
            uint32_t l0, l1, l2, l3;
            uint32_t h0 = split_pair(rx0.x, rx0.y, l0);
            uint32_t h1 = split_pair(rx0.z, rx0.w, l1);
            uint32_t h2 = split_pair(rx1.x, rx1.y, l2);
            uint32_t h3 = split_pair(rx1.z, rx1.w, l3);
            uint32_t dstb = sb + S_A + (uint32_t)((s + 1) & 1) * 8192u + prow_off(arow, au);
            asm volatile("st.shared.v4.b32 [%0], {%1,%2,%3,%4};"
                         :: "r"(dstb), "r"(h0), "r"(h1), "r"(h2), "r"(h3) : "memory");
            asm volatile("st.shared.v4.b32 [%0], {%1,%2,%3,%4};"
                         :: "r"(dstb + 4096), "r"(l0), "r"(l1), "r"(l2), "r"(l3) : "memory");
            if (s < 6) {
                rx0 = *(const float4*)(gA + (s + 2) * 32);
                rx1 = *(const float4*)(gA + (s + 2) * 32 + 4);
            }
            CP_WAIT_ALL();     // B(s+1) complete
            __syncthreads();
        }
        // s == 7: fall straight into epilogue
    }

    // ---- epilogue: direct from fragments (overlaps peer CTA's MMA phase) ----
    {
        float2 bb[8];
        #pragma unroll
        for (int nt = 0; nt < 8; nt++) {
            int cc = warp_n * 64 + nt * 8 + (lane & 3) * 2;
            bb[nt] = *(const float2*)(b_edge + cc);
        }
        #pragma unroll
        for (int mt = 0; mt < 2; mt++) {
            #pragma unroll
            for (int rh = 0; rh < 2; rh++) {
                int r = warp_m * 32 + mt * 16 + rh * 8 + (lane >> 2);
                int e = tile * 64 + r;
                int sN = ((const int*)(smem + S_IDX))[r];
                int dN = ((const int*)(smem + S_IDX + 256))[r];
                const float* pe1 = g_esrc + (size_t)sN * DD;
                const float* pe2 = g_edst + (size_t)dN * DD;
                const float* pf  = g_fsrc + (size_t)sN * DD;
                float* pm = m_out + (size_t)e * DD;
                float* pa = g_agg + (size_t)dN * DD;
                #pragma unroll
                for (int nt = 0; nt < 8; nt++) {
                    int cc = warp_n * 64 + nt * 8 + (lane & 3) * 2;
                    float a0 = acc[mt][nt][rh * 2 + 0];
                    float a1 = acc[mt][nt][rh * 2 + 1];
                    float2 e1 = *(const float2*)(pe1 + cc);
                    float2 e2 = *(const float2*)(pe2 + cc);
                    float2 f  = *(const float2*)(pf + cc);
                    float mx = a0 + bb[nt].x + e1.x + e2.x;
                    float my = a1 + bb[nt].y + e1.y + e2.y;
                    *(float2*)(pm + cc) = make_float2(mx, my);
                    float s0 = f.x / (1.f + __expf(-mx));
                    float s1 = f.y / (1.f + __expf(-my));
                    asm volatile("red.global.add.v2.f32 [%0], {%1,%2};"
                                 :: "l"(pa + cc), "f"(s0), "f"(s1) : "memory");
                }
            }
        }
    }
    CP_WAIT_ALL();
}

// ---- SIMT GEMM 64x64x16 for node-sized matmuls ----
// MODE 0: z=0 -> esrc (+ fsrc rows), z=1 -> edst
// MODE 3: rst = nodef + (g_agg@weight)*indeg^-1/2 + bias
template <int MODE>
__global__ void __launch_bounds__(256)
gemm_kernel(const float* __restrict__ A_in, const float* __restrict__ B0,
            const float* __restrict__ bias0, const float* __restrict__ B1,
            const float* __restrict__ bias1, float* __restrict__ C, int M,
            const float* __restrict__ nodef)
{
    const float* A = (MODE == 3) ? (const float*)g_agg : A_in;
    const float* B = (MODE == 0 && blockIdx.z) ? B1 : B0;
    const float* bias = (MODE == 0 && blockIdx.z) ? bias1 : bias0;

    constexpr int BM = 64, BN = 64, BK = 16;
    __shared__ float As[BK][BM + 1];
    __shared__ float Bs[BK][BN];

    const int tid = threadIdx.x;
    const int tx = tid & 15, ty = tid >> 4;
    const int bm0 = blockIdx.y * BM, bn0 = blockIdx.x * BN;
    const int lrow = tid >> 2, lk = (tid & 3) * 4;
    const int brow = tid >> 4, bcol = (tid & 15) * 4;

    float acc[4][4];
    #pragma unroll
    for (int i = 0; i < 4; i++)
        #pragma unroll
        for (int j = 0; j < 4; j++) acc[i][j] = 0.f;

    const int ty4 = ty * 4, tx4 = tx * 4;
    for (int k0 = 0; k0 < DD; k0 += BK) {
        float4 av;
        int ar = bm0 + lrow;
        if (ar < M) av = *(const float4*)(A + (size_t)ar * DD + k0 + lk);
        else        av = make_float4(0.f, 0.f, 0.f, 0.f);
        As[lk + 0][lrow] = av.x; As[lk + 1][lrow] = av.y;
        As[lk + 2][lrow] = av.z; As[lk + 3][lrow] = av.w;
        *(float4*)&Bs[brow][bcol] = *(const float4*)(B + (size_t)(k0 + brow) * DD + bn0 + bcol);
        __syncthreads();
        #pragma unroll
        for (int kk = 0; kk < BK; kk++) {
            float a0 = As[kk][ty4 + 0], a1 = As[kk][ty4 + 1];
            float a2 = As[kk][ty4 + 2], a3 = As[kk][ty4 + 3];
            float4 b = *(float4*)&Bs[kk][tx4];
            acc[0][0] += a0 * b.x; acc[0][1] += a0 * b.y; acc[0][2] += a0 * b.z; acc[0][3] += a0 * b.w;
            acc[1][0] += a1 * b.x; acc[1][1] += a1 * b.y; acc[1][2] += a1 * b.z; acc[1][3] += a1 * b.w;
            acc[2][0] += a2 * b.x; acc[2][1] += a2 * b.y; acc[2][2] += a2 * b.z; acc[2][3] += a2 * b.w;
            acc[3][0] += a3 * b.x; acc[3][1] += a3 * b.y; acc[3][2] += a3 * b.z; acc[3][3] += a3 * b.w;
        }
        __syncthreads();
    }

    const float4 bb = *(const float4*)(bias + bn0 + tx4);
    const size_t coloff = (size_t)(bn0 + tx4);
    #pragma unroll
    for (int i = 0; i < 4; i++) {
        int r = bm0 + ty4 + i;
        if (r >= M) continue;
        if (MODE == 0) {
            float4 o;
            o.x = acc[i][0] + bb.x; o.y = acc[i][1] + bb.y;
            o.z = acc[i][2] + bb.z; o.w = acc[i][3] + bb.w;
            float* dstp = blockIdx.z ? g_edst : g_esrc;
            *(float4*)(dstp + (size_t)r * DD + coloff) = o;
            if (blockIdx.z == 0) {
                float nrm = rsqrtf(fmaxf(g_outdeg[r], 1.f));
                const float4 nf = *(const float4*)(nodef + (size_t)r * DD + coloff);
                float4 fo;
                fo.x = nf.x * nrm; fo.y = nf.y * nrm;
                fo.z = nf.z * nrm; fo.w = nf.w * nrm;
                *(float4*)(g_fsrc + (size_t)r * DD + coloff) = fo;
            }
        } else {
            float nrm = rsqrtf(fmaxf(g_indeg[r], 1.f));
            const float4 nf = *(const float4*)(nodef + (size_t)r * DD + coloff);
            float4 o;
            o.x = nf.x + acc[i][0] * nrm + bb.x;
            o.y = nf.y + acc[i][1] * nrm + bb.y;
            o.z = nf.z + acc[i][2] * nrm + bb.z;
            o.w = nf.w + acc[i][3] * nrm + bb.w;
            *(float4*)(C + (size_t)r * DD + coloff) = o;
        }
    }
}

extern "C" void kernel_launch(void* const* d_in, const int* in_sizes, int n_in,
                              void* d_out, int out_size) {
    const float* nodef  = (const float*)d_in[0];
    const float* edgef  = (const float*)d_in[1];
    const int*   src    = (const int*)d_in[2];
    const int*   dst    = (const int*)d_in[3];
    const float* weight = (const float*)d_in[4];
    const float* bias   = (const float*)d_in[5];
    const float* w_src  = (const float*)d_in[6];
    const float* b_src  = (const float*)d_in[7];
    const float* w_dst  = (const float*)d_in[8];
    const float* b_dst  = (const float*)d_in[9];
    const float* w_edge = (const float*)d_in[10];
    const float* b_edge = (const float*)d_in[11];

    float* rst   = (float*)d_out;             // [N, D]
    float* m_out = rst + (size_t)NN * DD;     // [E, D]

    static bool attr_set = false;
    if (!attr_set) {
        cudaFuncSetAttribute(edge_mma_kernel, cudaFuncAttributeMaxDynamicSharedMemorySize, S_TOTAL);
        attr_set = true;
    }

    // launch 0: weight prep + zero
    fuse0_kernel<<<(NN * DD + 255) / 256, 256>>>(w_edge);
    // launch 1: degrees
    degree_kernel<<<(EE + 255) / 256, 256>>>(src, dst);
    // launch 2: e_src (+fsrc) / e_dst
    {
        dim3 g(DD / 64, (NN + 63) / 64, 2);
        gemm_kernel<0><<<g, 256>>>(nodef, w_src, b_src, w_dst, b_dst, nullptr, NN, nodef);
    }
    // launch 3 (profiled): edge GEMM + fused epilogue
    edge_mma_kernel<<<EE / 64, 256, S_TOTAL>>>(edgef, src, dst, b_edge, m_out);
    // launch 4: final projection + norm + bias + residual
    {
        dim3 g(DD / 64, (NN + 63) / 64, 1);
        gemm_kernel<3><<<g, 256>>>(nullptr, weight, bias, nullptr, nullptr, rst, NN, nodef);
    }
}

// round 11
// speedup vs baseline: 1.8602x; 1.1183x over previous
#include <cuda_runtime.h>
#include <cuda_bf16.h>
#include <cstdint>

#define NN 10000
#define EE 320000
#define DD 256

// ---------------- scratch (static device globals; no allocation) ----------------
__device__ float g_esrc[NN * DD];
__device__ float g_edst[NN * DD];
__device__ float g_fsrc[NN * DD];
__device__ float g_agg[NN * DD];
__device__ float g_outdeg[NN];
__device__ float g_indeg[NN];
// w_edge^T split bf16 hi/lo, pre-swizzled per K32 chunk in the paired-row layout:
// 16B-unit index = c*1024 + (n>>1)*8 + (n&1)*4 + (u ^ ((n>>1)&3)),  u = k8-unit (0..3)
__device__ uint4 g_Bswhi[8 * 1024];
__device__ uint4 g_Bswlo[8 * 1024];

// ---------------- helpers ----------------
__device__ __forceinline__ uint32_t smem_to_u32(const void* p) {
    uint32_t a;
    asm("{ .reg .u64 t; cvta.to.shared.u64 t, %1; cvt.u32.u64 %0, t; }" : "=r"(a) : "l"(p));
    return a;
}
__device__ __forceinline__ void ldm_x4(uint32_t& r0, uint32_t& r1, uint32_t& r2, uint32_t& r3,
                                       uint32_t addr) {
    asm volatile("ldmatrix.sync.aligned.m8n8.x4.shared.b16 {%0,%1,%2,%3}, [%4];"
                 : "=r"(r0), "=r"(r1), "=r"(r2), "=r"(r3) : "r"(addr));
}
__device__ __forceinline__ void mma16816(float* c, const uint32_t* a, const uint32_t* b) {
    asm volatile(
        "mma.sync.aligned.m16n8k16.row.col.f32.bf16.bf16.f32 "
        "{%0,%1,%2,%3}, {%4,%5,%6,%7}, {%8,%9}, {%0,%1,%2,%3};"
        : "+f"(c[0]), "+f"(c[1]), "+f"(c[2]), "+f"(c[3])
        : "r"(a[0]), "r"(a[1]), "r"(a[2]), "r"(a[3]), "r"(b[0]), "r"(b[1]));
}
#define CP_ASYNC16(saddr, gptr) \
    asm volatile("cp.async.cg.shared.global [%0], [%1], 16;" :: "r"(saddr), "l"(gptr) : "memory")
#define CP_COMMIT() asm volatile("cp.async.commit_group;" ::: "memory")
#define CP_WAIT_ALL() asm volatile("cp.async.wait_group 0;" ::: "memory")

__device__ __forceinline__ uint32_t split_pair(float a, float b, uint32_t& lo) {
    __nv_bfloat16 ha = __float2bfloat16(a), hb = __float2bfloat16(b);
    __nv_bfloat16 la = __float2bfloat16(a - __bfloat162float(ha));
    __nv_bfloat16 lb = __float2bfloat16(b - __bfloat162float(hb));
    lo = ((uint32_t)__bfloat16_as_ushort(lb) << 16) | (uint32_t)__bfloat16_as_ushort(la);
    return ((uint32_t)__bfloat16_as_ushort(hb) << 16) | (uint32_t)__bfloat16_as_ushort(ha);
}

// ---------------- launch 0: weight prep + zero (fused) ----------------
__global__ void fuse0_kernel(const float* __restrict__ w_edge) {
    int t = blockIdx.x * blockDim.x + threadIdx.x;
    if (t < NN * DD) g_agg[t] = 0.f;
    if (t < NN) { g_outdeg[t] = 0.f; g_indeg[t] = 0.f; }
    if (t < 8192) {
        int n = t & 255;
        int g = t >> 8;                 // 0..31
        int c = g >> 2, u = g & 3;      // K32 chunk, k8-unit
        uint32_t h[4], l[4];
        #pragma unroll
        for (int j = 0; j < 4; j++) {
            int k = c * 32 + u * 8 + 2 * j;
            float a = w_edge[(size_t)k * DD + n];
            float b = w_edge[(size_t)(k + 1) * DD + n];
            h[j] = split_pair(a, b, l[j]);
        }
        int di = c * 1024 + (n >> 1) * 8 + (n & 1) * 4 + (u ^ ((n >> 1) & 3));
        g_Bswhi[di] = make_uint4(h[0], h[1], h[2], h[3]);
        g_Bswlo[di] = make_uint4(l[0], l[1], l[2], l[3]);
    }
}

// ---------------- launch 1: degrees ----------------
__global__ void degree_kernel(const int* __restrict__ src, const int* __restrict__ dst) {
    int e = blockIdx.x * blockDim.x + threadIdx.x;
    if (e < EE) {
        atomicAdd(&g_outdeg[src[e]], 1.f);
        atomicAdd(&g_indeg[dst[e]], 1.f);
    }
}

// ---------------- SMEM layout for edge kernel (per CTA) ----------------
// B ring: 2 slots x 32KB (hi 16KB @ +0, lo 16KB @ +16384) = 64KB
static constexpr int S_B   = 0;
static constexpr int S_A   = 65536;      // 2 bufs x 8KB (hi 4KB + lo 4KB) = 16KB
static constexpr int S_IDX = 81920;      // 64 src + 64 dst ints = 512B
static constexpr int S_TOTAL = 82432;    // ~81KB -> 2 CTAs/SM

// paired-row swizzled offset for a (row, k8-unit) 16B tile
__device__ __forceinline__ uint32_t prow_off(uint32_t r, uint32_t u) {
    return (r >> 1) * 128u + (r & 1) * 64u + ((u ^ ((r >> 1) & 3u)) << 4);
}

// ---------------- launch 3: edge GEMM (256 threads, 2 CTAs/SM, bf16x3) ----------------
__global__ void __launch_bounds__(256, 2)
edge_mma_kernel(const float* __restrict__ edgef, const int* __restrict__ src,
                const int* __restrict__ dst, const float* __restrict__ b_edge,
                float* __restrict__ m_out)
{
    extern __shared__ char smem[];
    const uint32_t sb = smem_to_u32(smem);
    const int tid = threadIdx.x;
    const int lane = tid & 31;
    const int wid = tid >> 5;
    const int warp_m = wid & 1;       // rows 32*warp_m (64-edge tile)
    const int warp_n = wid >> 1;      // cols 64*warp_n
    const int tile = blockIdx.x;      // 64 edges

    float acc[2][8][4];
    #pragma unroll
    for (int mt = 0; mt < 2; mt++)
        #pragma unroll
        for (int nt = 0; nt < 8; nt++)
            #pragma unroll
            for (int i = 0; i < 4; i++) acc[mt][nt][i] = 0.f;

    // A mapping: thread -> (row, k8-unit); 64 rows x 4 units = 256 threads
    const int arow = tid >> 2;
    const int au = tid & 3;
    const float* gA = edgef + (size_t)(tile * 64 + arow) * DD + au * 8;

    // ---- prologue ----
    // B chunk 0 into slot 0
    {
        const uint4* bh = g_Bswhi;
        const uint4* bl = g_Bswlo;
        #pragma unroll
        for (int i = 0; i < 4; i++) {
            int idx = tid + i * 256;     // 0..1023
            CP_ASYNC16(sb + S_B + idx * 16,         bh + idx);
            CP_ASYNC16(sb + S_B + 16384 + idx * 16, bl + idx);
        }
        CP_COMMIT();
    }
    if (tid < 64) {
        ((int*)(smem + S_IDX))[tid] = src[tile * 64 + tid];
        ((int*)(smem + S_IDX + 256))[tid] = dst[tile * 64 + tid];
    }
    // A(0): load + convert into Abuf0
    float4 rx0 = *(const float4*)(gA);
    float4 rx1 = *(const float4*)(gA + 4);
    {
        uint32_t l0, l1, l2, l3;
        uint32_t h0 = split_pair(rx0.x, rx0.y, l0);
        uint32_t h1 = split_pair(rx0.z, rx0.w, l1);
        uint32_t h2 = split_pair(rx1.x, rx1.y, l2);
        uint32_t h3 = split_pair(rx1.z, rx1.w, l3);
        uint32_t off = prow_off(arow, au);
        *(uint4*)(smem + S_A + off) = make_uint4(h0, h1, h2, h3);
        *(uint4*)(smem + S_A + 4096 + off) = make_uint4(l0, l1, l2, l3);
    }
    // prefetch A(1) into regs
    rx0 = *(const float4*)(gA + 32);
    rx1 = *(const float4*)(gA + 36);

    CP_WAIT_ALL();       // B(0) done
    __syncthreads();

    const uint32_t a_row = (uint32_t)(lane & 15);
    const uint32_t a_kh  = (uint32_t)(lane >> 4);
    const uint32_t b_nl  = (uint32_t)((lane & 7) + ((lane >> 4) << 3));
    const uint32_t b_kh  = (uint32_t)((lane >> 3) & 1);

    // ---- mainloop: 8 stages (one K32 chunk each, 3 split terms) ----
    #pragma unroll 1
    for (int s = 0; s < 8; s++) {
        const uint32_t bbase = sb + S_B + (uint32_t)(s & 1) * 32768u;
        const uint32_t abase = sb + S_A + (uint32_t)(s & 1) * 8192u;

        // issue B(s+1) into slot (s+1)&1 — last read in stage s-1, behind barrier
        if (s < 7) {
            const uint4* bh = g_Bswhi + (s + 1) * 1024;
            const uint4* bl = g_Bswlo + (s + 1) * 1024;
            const uint32_t slot = sb + S_B + (uint32_t)((s + 1) & 1) * 32768u;
            #pragma unroll
            for (int i = 0; i < 4; i++) {
                int idx = tid + i * 256;
                CP_ASYNC16(slot + idx * 16,         bh + idx);
                CP_ASYNC16(slot + 16384 + idx * 16, bl + idx);
            }
            CP_COMMIT();
        }

        // ---- MMA: 2 k16 steps, 3 terms each ----
        #pragma unroll
        for (int ks = 0; ks < 2; ks++) {
            uint32_t ah[2][4], al[2][4];
            #pragma unroll
            for (int mt = 0; mt < 2; mt++) {
                uint32_t r = (uint32_t)(warp_m * 32 + mt * 16) + a_row;
                uint32_t u = (uint32_t)(ks * 2) + a_kh;
                uint32_t off = prow_off(r, u);
                ldm_x4(ah[mt][0], ah[mt][1], ah[mt][2], ah[mt][3], abase + off);
                ldm_x4(al[mt][0], al[mt][1], al[mt][2], al[mt][3], abase + 4096 + off);
            }
            #pragma unroll
            for (int j = 0; j < 4; j++) {
                uint32_t n = (uint32_t)(warp_n * 64 + j * 16) + b_nl;
                uint32_t u = (uint32_t)(ks * 2) + b_kh;
                uint32_t boff = prow_off(n, u);
                uint32_t bh[4], bl[4];
                ldm_x4(bh[0], bh[1], bh[2], bh[3], bbase + boff);
                ldm_x4(bl[0], bl[1], bl[2], bl[3], bbase + 16384 + boff);
                #pragma unroll
                for (int mt = 0; mt < 2; mt++) {
                    mma16816(acc[mt][2 * j + 0], ah[mt], bh + 0);
                    mma16816(acc[mt][2 * j + 1], ah[mt], bh + 2);
                    mma16816(acc[mt][2 * j + 0], al[mt], bh + 0);
                    mma16816(acc[mt][2 * j + 1], al[mt], bh + 2);
                    mma16816(acc[mt][2 * j + 0], ah[mt], bl + 0);
                    mma16816(acc[mt][2 * j + 1], ah[mt], bl + 2);
                }
            }
        }

        // ---- convert A(s+1) into other A buffer; prefetch A(s+2) ----
        if (s < 7) {
            uint32_t l0, l1, l2, l3;
            uint32_t h0 = split_pair(rx0.x, rx0.y, l0);
            uint32_t h1 = split_pair(rx0.z, rx0.w, l1);
            uint32_t h2 = split_pair(rx1.x, rx1.y, l2);
            uint32_t h3 = split_pair(rx1.z, rx1.w, l3);
            uint32_t dstb = sb + S_A + (uint32_t)((s + 1) & 1) * 8192u + prow_off(arow, au);
            asm volatile("st.shared.v4.b32 [%0], {%1,%2,%3,%4};"
                         :: "r"(dstb), "r"(h0), "r"(h1), "r"(h2), "r"(h3) : "memory");
            asm volatile("st.shared.v4.b32 [%0], {%1,%2,%3,%4};"
                         :: "r"(dstb + 4096), "r"(l0), "r"(l1), "r"(l2), "r"(l3) : "memory");
            if (s < 6) {
                rx0 = *(const float4*)(gA + (s + 2) * 32);
                rx1 = *(const float4*)(gA + (s + 2) * 32 + 4);
            }
            CP_WAIT_ALL();     // B(s+1) complete
            __syncthreads();
        }
        // s == 7: fall straight into epilogue
    }

    // ---- epilogue: float4 via quad shfl_xor exchange ----
    {
        const int q = lane & 3;
        const int odd = q & 1;
        // column base for this lane's float4 per nt-pair ntp:
        // cc = warp_n*64 + ntp*16 + (q>>1)*4 + (q&1)*8
        const int ccl = warp_n * 64 + ((q >> 1) << 2) + (odd << 3);

        // bias float4s (uniform over rows), one per nt-pair
        float4 bbv[4];
        #pragma unroll
        for (int ntp = 0; ntp < 4; ntp++)
            bbv[ntp] = *(const float4*)(b_edge + ccl + ntp * 16);

        #pragma unroll
        for (int mt = 0; mt < 2; mt++) {
            #pragma unroll
            for (int rh = 0; rh < 2; rh++) {
                int r = warp_m * 32 + mt * 16 + rh * 8 + (lane >> 2);
                int e = tile * 64 + r;
                int sN = ((const int*)(smem + S_IDX))[r];
                int dN = ((const int*)(smem + S_IDX + 256))[r];
                const float* pe1 = g_esrc + (size_t)sN * DD;
                const float* pe2 = g_edst + (size_t)dN * DD;
                const float* pf  = g_fsrc + (size_t)sN * DD;
                float* pm = m_out + (size_t)e * DD;
                float* pa = g_agg + (size_t)dN * DD;
                #pragma unroll
                for (int ntp = 0; ntp < 4; ntp++) {
                    float v0x = acc[mt][2 * ntp + 0][rh * 2 + 0];
                    float v0y = acc[mt][2 * ntp + 0][rh * 2 + 1];
                    float v1x = acc[mt][2 * ntp + 1][rh * 2 + 0];
                    float v1y = acc[mt][2 * ntp + 1][rh * 2 + 1];
                    float t0 = __shfl_xor_sync(0xffffffffu, v0x, 1);
                    float t1 = __shfl_xor_sync(0xffffffffu, v0y, 1);
                    float t2 = __shfl_xor_sync(0xffffffffu, v1x, 1);
                    float t3 = __shfl_xor_sync(0xffffffffu, v1y, 1);
                    // even lane: tile 2ntp cols (v0, partner v0); odd: tile 2ntp+1 (partner v1, v1)
                    float4 dv;
                    dv.x = odd ? t2  : v0x;
                    dv.y = odd ? t3  : v0y;
                    dv.z = odd ? v1x : t0;
                    dv.w = odd ? v1y : t1;

                    int cc = ccl + ntp * 16;
                    float4 bb = bbv[ntp];
                    float4 e1 = *(const float4*)(pe1 + cc);
                    float4 e2 = *(const float4*)(pe2 + cc);
                    float4 f  = *(const float4*)(pf + cc);
                    float4 mv;
                    mv.x = dv.x + bb.x + e1.x + e2.x;
                    mv.y = dv.y + bb.y + e1.y + e2.y;
                    mv.z = dv.z + bb.z + e1.z + e2.z;
                    mv.w = dv.w + bb.w + e1.w + e2.w;
                    *(float4*)(pm + cc) = mv;
                    float s0 = f.x / (1.f + __expf(-mv.x));
                    float s1 = f.y / (1.f + __expf(-mv.y));
                    float s2 = f.z / (1.f + __expf(-mv.z));
                    float s3 = f.w / (1.f + __expf(-mv.w));
                    asm volatile("red.global.add.v4.f32 [%0], {%1,%2,%3,%4};"
                                 :: "l"(pa + cc), "f"(s0), "f"(s1), "f"(s2), "f"(s3) : "memory");
                }
            }
        }
    }
    CP_WAIT_ALL();
}

// ---- SIMT GEMM 64x64x16 for node-sized matmuls ----
// MODE 0: z=0 -> esrc (+ fsrc rows), z=1 -> edst
// MODE 3: rst = nodef + (g_agg@weight)*indeg^-1/2 + bias
template <int MODE>
__global__ void __launch_bounds__(256)
gemm_kernel(const float* __restrict__ A_in, const float* __restrict__ B0,
            const float* __restrict__ bias0, const float* __restrict__ B1,
            const float* __restrict__ bias1, float* __restrict__ C, int M,
            const float* __restrict__ nodef)
{
    const float* A = (MODE == 3) ? (const float*)g_agg : A_in;
    const float* B = (MODE == 0 && blockIdx.z) ? B1 : B0;
    const float* bias = (MODE == 0 && blockIdx.z) ? bias1 : bias0;

    constexpr int BM = 64, BN = 64, BK = 16;
    __shared__ float As[BK][BM + 1];
    __shared__ float Bs[BK][BN];

    const int tid = threadIdx.x;
    const int tx = tid & 15, ty = tid >> 4;
    const int bm0 = blockIdx.y * BM, bn0 = blockIdx.x * BN;
    const int lrow = tid >> 2, lk = (tid & 3) * 4;
    const int brow = tid >> 4, bcol = (tid & 15) * 4;

    float acc[4][4];
    #pragma unroll
    for (int i = 0; i < 4; i++)
        #pragma unroll
        for (int j = 0; j < 4; j++) acc[i][j] = 0.f;

    const int ty4 = ty * 4, tx4 = tx * 4;
    for (int k0 = 0; k0 < DD; k0 += BK) {
        float4 av;
        int ar = bm0 + lrow;
        if (ar < M) av = *(const float4*)(A + (size_t)ar * DD + k0 + lk);
        else        av = make_float4(0.f, 0.f, 0.f, 0.f);
        As[lk + 0][lrow] = av.x; As[lk + 1][lrow] = av.y;
        As[lk + 2][lrow] = av.z; As[lk + 3][lrow] = av.w;
        *(float4*)&Bs[brow][bcol] = *(const float4*)(B + (size_t)(k0 + brow) * DD + bn0 + bcol);
        __syncthreads();
        #pragma unroll
        for (int kk = 0; kk < BK; kk++) {
            float a0 = As[kk][ty4 + 0], a1 = As[kk][ty4 + 1];
            float a2 = As[kk][ty4 + 2], a3 = As[kk][ty4 + 3];
            float4 b = *(float4*)&Bs[kk][tx4];
            acc[0][0] += a0 * b.x; acc[0][1] += a0 * b.y; acc[0][2] += a0 * b.z; acc[0][3] += a0 * b.w;
            acc[1][0] += a1 * b.x; acc[1][1] += a1 * b.y; acc[1][2] += a1 * b.z; acc[1][3] += a1 * b.w;
            acc[2][0] += a2 * b.x; acc[2][1] += a2 * b.y; acc[2][2] += a2 * b.z; acc[2][3] += a2 * b.w;
            acc[3][0] += a3 * b.x; acc[3][1] += a3 * b.y; acc[3][2] += a3 * b.z; acc[3][3] += a3 * b.w;
        }
        __syncthreads();
    }

    const float4 bb = *(const float4*)(bias + bn0 + tx4);
    const size_t coloff = (size_t)(bn0 + tx4);
    #pragma unroll
    for (int i = 0; i < 4; i++) {
        int r = bm0 + ty4 + i;
        if (r >= M) continue;
        if (MODE == 0) {
            float4 o;
            o.x = acc[i][0] + bb.x; o.y = acc[i][1] + bb.y;
            o.z = acc[i][2] + bb.z; o.w = acc[i][3] + bb.w;
            float* dstp = blockIdx.z ? g_edst : g_esrc;
            *(float4*)(dstp + (size_t)r * DD + coloff) = o;
            if (blockIdx.z == 0) {
                float nrm = rsqrtf(fmaxf(g_outdeg[r], 1.f));
                const float4 nf = *(const float4*)(nodef + (size_t)r * DD + coloff);
                float4 fo;
                fo.x = nf.x * nrm; fo.y = nf.y * nrm;
                fo.z = nf.z * nrm; fo.w = nf.w * nrm;
                *(float4*)(g_fsrc + (size_t)r * DD + coloff) = fo;
            }
        } else {
            float nrm = rsqrtf(fmaxf(g_indeg[r], 1.f));
            const float4 nf = *(const float4*)(nodef + (size_t)r * DD + coloff);
            float4 o;
            o.x = nf.x + acc[i][0] * nrm + bb.x;
            o.y = nf.y + acc[i][1] * nrm + bb.y;
            o.z = nf.z + acc[i][2] * nrm + bb.z;
            o.w = nf.w + acc[i][3] * nrm + bb.w;
            *(float4*)(C + (size_t)r * DD + coloff) = o;
        }
    }
}

extern "C" void kernel_launch(void* const* d_in, const int* in_sizes, int n_in,
                              void* d_out, int out_size) {
    const float* nodef  = (const float*)d_in[0];
    const float* edgef  = (const float*)d_in[1];
    const int*   src    = (const int*)d_in[2];
    const int*   dst    = (const int*)d_in[3];
    const float* weight = (const float*)d_in[4];
    const float* bias   = (const float*)d_in[5];
    const float* w_src  = (const float*)d_in[6];
    const float* b_src  = (const float*)d_in[7];
    const float* w_dst  = (const float*)d_in[8];
    const float* b_dst  = (const float*)d_in[9];
    const float* w_edge = (const float*)d_in[10];
    const float* b_edge = (const float*)d_in[11];

    float* rst   = (float*)d_out;             // [N, D]
    float* m_out = rst + (size_t)NN * DD;     // [E, D]

    static bool attr_set = false;
    if (!attr_set) {
        cudaFuncSetAttribute(edge_mma_kernel, cudaFuncAttributeMaxDynamicSharedMemorySize, S_TOTAL);
        attr_set = true;
    }

    // launch 0: weight prep + zero
    fuse0_kernel<<<(NN * DD + 255) / 256, 256>>>(w_edge);
    // launch 1: degrees
    degree_kernel<<<(EE + 255) / 256, 256>>>(src, dst);
    // launch 2: e_src (+fsrc) / e_dst
    {
        dim3 g(DD / 64, (NN + 63) / 64, 2);
        gemm_kernel<0><<<g, 256>>>(nodef, w_src, b_src, w_dst, b_dst, nullptr, NN, nodef);
    }
    // launch 3 (profiled): edge GEMM + fused epilogue
    edge_mma_kernel<<<EE / 64, 256, S_TOTAL>>>(edgef, src, dst, b_edge, m_out);
    // launch 4: final projection + norm + bias + residual
    {
        dim3 g(DD / 64, (NN + 63) / 64, 1);
        gemm_kernel<3><<<g, 256>>>(nullptr, weight, bias, nullptr, nullptr, rst, NN, nodef);
    }
}